// round 8
// baseline (speedup 1.0000x reference)
#include <cuda_runtime.h>
#include <cstdint>

#define BN 128
#define TT 512
#define NR 512
#define NOUT 512
#define NGRP 4          // batch groups of 32 rows
#define PN 64           // CTAs (neuron slices) per group
#define MB 32
#define NJ 8            // neurons per CTA slice
#define NTH 256
#define DT_TAU 0.2f

typedef unsigned long long u64;

// ---------------- global scratch ---------------------------------------------
__device__ float g_h[BN * NR];
__device__ float g_rh[BN * NR];
__device__ unsigned g_arr[NGRP][PN];
__device__ unsigned g_gen[NGRP];

// ---------------- f32x2 helpers ----------------------------------------------
__device__ __forceinline__ u64 ffma2(u64 a, u64 b, u64 c) {
    u64 d;
    asm("fma.rn.f32x2 %0, %1, %2, %3;" : "=l"(d) : "l"(a), "l"(b), "l"(c));
    return d;
}
__device__ __forceinline__ u64 addf2(u64 a, u64 b) {
    u64 d;
    asm("add.rn.f32x2 %0, %1, %2;" : "=l"(d) : "l"(a), "l"(b));
    return d;
}
__device__ __forceinline__ u64 pack2(float lo, float hi) {
    u64 d;
    asm("mov.b64 %0, {%1, %2};" : "=l"(d) : "f"(lo), "f"(hi));
    return d;
}
__device__ __forceinline__ float2 unpack2(u64 d) {
    float2 r;
    asm("mov.b64 {%0, %1}, %2;" : "=f"(r.x), "=f"(r.y) : "l"(d));
    return r;
}
__device__ __forceinline__ unsigned ld_acq(const unsigned* p) {
    unsigned v;
    asm volatile("ld.acquire.gpu.u32 %0, [%1];" : "=r"(v) : "l"(p) : "memory");
    return v;
}
__device__ __forceinline__ void st_rel(unsigned* p, unsigned v) {
    asm volatile("st.release.gpu.u32 [%0], %1;" :: "l"(p), "r"(v) : "memory");
}
__device__ __forceinline__ void cp16(unsigned dst, const void* src) {
    asm volatile("cp.async.cg.shared.global [%0], [%1], 16;"
                 :: "r"(dst), "l"(src) : "memory");
}
__device__ __forceinline__ void cp8(unsigned dst, const void* src) {
    asm volatile("cp.async.ca.shared.global [%0], [%1], 8;"
                 :: "r"(dst), "l"(src) : "memory");
}
#define CP_COMMIT() asm volatile("cp.async.commit_group;" ::: "memory")
#define CP_WAIT(N)  asm volatile("cp.async.wait_group %0;" :: "n"(N) : "memory")

// ---------------- SMEM layout ------------------------------------------------
// WZR : [k][4 pairs x {z,r}x2 neurons] floats : 512*16*4 = 32768
// WH2 : [jp][k] packed-pair u64, row 514 u64  : 4*514*8  = 16448
// HS0/HS1 : 32 rows x (512 f + 16B pad)       : 2*66048
// XT0/XT1 : 32 float2 each
// WZRX : 16 u64 ; WHX : 8 u64 ; PART : 128 x 16B
#define WZR_OFF   0
#define WH2_OFF   32768
#define WH2_ROWD  514
#define HS0_OFF   (WH2_OFF + 4 * WH2_ROWD * 8)    // 49216
#define HS_STRIDE 2064
#define HS_BYTES  (MB * HS_STRIDE)                // 66048
#define HS1_OFF   (HS0_OFF + HS_BYTES)            // 115264
#define XT0_OFF   (HS1_OFF + HS_BYTES)            // 181312
#define XT1_OFF   (XT0_OFF + 256)
#define WZRX_OFF  (XT1_OFF + 256)
#define WHX_OFF   (WZRX_OFF + 128)
#define PART_OFF  (WHX_OFF + 64)
#define SMEM_TOTAL (PART_OFF + 2048)              // 184064

// ---------------- split group barrier ----------------------------------------
__device__ __forceinline__ void bar_arrive(int g, int gn, int tid, unsigned tgt) {
    // caller must have executed __syncthreads() after its global stores
    if (tid == 0) st_rel(&g_arr[g][gn], tgt);
}
__device__ __forceinline__ void bar_wait(int g, int gn, int tid, unsigned tgt) {
    if (gn == 0) {
        if (tid < 32) {
            unsigned v0, v1;
            do {
                v0 = ld_acq(&g_arr[g][tid]);
                v1 = ld_acq(&g_arr[g][tid + 32]);
            } while (!__all_sync(0xffffffffu, (v0 >= tgt) && (v1 >= tgt)));
            if (tid == 0) st_rel(&g_gen[g], tgt);
        }
    } else if (tid == 0) {
        while (ld_acq(&g_gen[g]) < tgt) {}
    }
    __syncthreads();
}

__global__ void init_bar_kernel() {
    int i = threadIdx.x;
    if (i < NGRP * PN) ((unsigned*)g_arr)[i] = 0u;
    if (i < NGRP) g_gen[i] = 0u;
}

// ---------------- async staging: 32 rows x 512 floats -> HS buffer -----------
__device__ __forceinline__ void issue_stage(const float* __restrict__ src,
                                            unsigned hs_u32, const float* xsrc,
                                            unsigned xt_u32, int b0, int tnext,
                                            bool do_x, int tid) {
    int row = tid >> 3, c0 = tid & 7;
    const float4* s = (const float4*)(src + (size_t)(b0 + row) * NR) + c0;
    unsigned d = hs_u32 + row * HS_STRIDE + c0 * 16;
#pragma unroll
    for (int i = 0; i < 16; i++) cp16(d + i * 128, s + 8 * i);
    if (do_x && tid < 32)
        cp8(xt_u32 + tid * 8, xsrc + ((size_t)(b0 + tid) * TT + tnext) * 2);
    CP_COMMIT();
}

// ---------------- phase 1: z, r, r*h ------------------------------------------
__device__ __forceinline__ void phase1(char* smem, int hs_off, int xt_off,
                                       int b0, int j0, int tid, int jp, int bb,
                                       int kh, float& z0o, float& z1o,
                                       float2& howno) {
    const int jj0 = 2 * jp;
    const int kb = kh * 256;
    const float4* hr = (const float4*)(smem + hs_off + bb * HS_STRIDE) + (kb >> 2);
    const ulonglong2* wz = (const ulonglong2*)(smem + WZR_OFF) + kb * 4 + jp;
    const u64* wzrx = (const u64*)(smem + WZRX_OFF);
    ulonglong2* PART = (ulonglong2*)(smem + PART_OFF);
    u64 a0, a1, a0b = 0ull, a1b = 0ull;
    if (kh == 0) {
        float2 xt = ((const float2*)(smem + xt_off))[bb];
        u64 x0p = pack2(xt.x, xt.x), x1p = pack2(xt.y, xt.y);
        a0 = ffma2(x0p, wzrx[jj0],     ffma2(x1p, wzrx[8 + jj0],     0ull));
        a1 = ffma2(x0p, wzrx[jj0 + 1], ffma2(x1p, wzrx[8 + jj0 + 1], 0ull));
    } else { a0 = 0ull; a1 = 0ull; }
#pragma unroll 8
    for (int k4 = 0; k4 < 64; k4++) {
        float4 v = hr[k4];
        u64 hx = pack2(v.x, v.x);
        ulonglong2 w0 = wz[(4 * k4 + 0) * 4];
        a0  = ffma2(hx, w0.x, a0);  a1  = ffma2(hx, w0.y, a1);
        u64 hy = pack2(v.y, v.y);
        ulonglong2 w1 = wz[(4 * k4 + 1) * 4];
        a0b = ffma2(hy, w1.x, a0b); a1b = ffma2(hy, w1.y, a1b);
        u64 hz = pack2(v.z, v.z);
        ulonglong2 w2 = wz[(4 * k4 + 2) * 4];
        a0  = ffma2(hz, w2.x, a0);  a1  = ffma2(hz, w2.y, a1);
        u64 hw = pack2(v.w, v.w);
        ulonglong2 w3 = wz[(4 * k4 + 3) * 4];
        a0b = ffma2(hw, w3.x, a0b); a1b = ffma2(hw, w3.y, a1b);
    }
    a0 = addf2(a0, a0b);
    a1 = addf2(a1, a1b);
    if (tid >= 128) PART[tid - 128] = make_ulonglong2(a0, a1);
    __syncthreads();
    if (tid < 128) {
        ulonglong2 pp = PART[tid];
        a0 = addf2(a0, pp.x);
        a1 = addf2(a1, pp.y);
        float2 zr0 = unpack2(a0), zr1 = unpack2(a1);
        float z0 = 1.f / (1.f + __expf(-zr0.x));
        float r0 = 1.f / (1.f + __expf(-zr0.y));
        float z1 = 1.f / (1.f + __expf(-zr1.x));
        float r1 = 1.f / (1.f + __expf(-zr1.y));
        float2 hown =
            *(const float2*)(smem + hs_off + bb * HS_STRIDE + (j0 + jj0) * 4);
        float2 rh = make_float2(r0 * hown.x, r1 * hown.y);
        *(float2*)&g_rh[(size_t)(b0 + bb) * NR + j0 + jj0] = rh;
        z0o = z0; z1o = z1; howno = hown;
    }
    __syncthreads();
}

// ---------------- phase 2: u, tanh, h update ----------------------------------
__device__ __forceinline__ void phase2(char* smem, int hs_off, int xt_off,
                                       int b0, int j0, int tid, int jp, int bb,
                                       int kh, int t, float z0, float z1,
                                       float2 hown, float* __restrict__ out_h) {
    const int jj0 = 2 * jp;
    const int kb = kh * 256;
    const float4* hr = (const float4*)(smem + hs_off + bb * HS_STRIDE) + (kb >> 2);
    const ulonglong2* w =
        (const ulonglong2*)(smem + WH2_OFF) + jp * (WH2_ROWD / 2) + (kb >> 1);
    const u64* whx = (const u64*)(smem + WHX_OFF);
    u64* PARTU = (u64*)(smem + PART_OFF);
    u64 uu, ub = 0ull;
    if (kh == 0) {
        float2 xt = ((const float2*)(smem + xt_off))[bb];
        u64 x0p = pack2(xt.x, xt.x), x1p = pack2(xt.y, xt.y);
        uu = ffma2(x0p, whx[jp], ffma2(x1p, whx[4 + jp], 0ull));
    } else uu = 0ull;
#pragma unroll 8
    for (int k4 = 0; k4 < 64; k4++) {
        float4 v = hr[k4];
        ulonglong2 wa = w[2 * k4];
        ulonglong2 wb = w[2 * k4 + 1];
        uu = ffma2(pack2(v.x, v.x), wa.x, uu);
        ub = ffma2(pack2(v.y, v.y), wa.y, ub);
        uu = ffma2(pack2(v.z, v.z), wb.x, uu);
        ub = ffma2(pack2(v.w, v.w), wb.y, ub);
    }
    uu = addf2(uu, ub);
    if (tid >= 128) PARTU[tid - 128] = uu;
    __syncthreads();
    if (tid < 128) {
        uu = addf2(uu, PARTU[tid]);
        float2 uf = unpack2(uu);
        float th0 = tanhf(uf.x), th1 = tanhf(uf.y);
        float2 hn;
        hn.x = hown.x + DT_TAU * (z0 - 1.f) * (hown.x - th0);
        hn.y = hown.y + DT_TAU * (z1 - 1.f) * (hown.y - th1);
        *(float2*)&g_h[(size_t)(b0 + bb) * NR + j0 + jj0] = hn;
        *(float2*)&out_h[((size_t)(b0 + bb) * TT + t) * NR + j0 + jj0] = hn;
    }
    __syncthreads();
}

// ---------------- persistent recurrent kernel ---------------------------------
__global__ void __launch_bounds__(NTH, 1)
rnn_persistent(const float* __restrict__ x, const float* __restrict__ init_state,
               const float* __restrict__ W_enc, const float* __restrict__ W_wz,
               const float* __restrict__ W_uz, const float* __restrict__ W_wr,
               const float* __restrict__ W_ur, const float* __restrict__ W_wh,
               const float* __restrict__ W_uh, float* __restrict__ out_h) {
    extern __shared__ char smem[];
    const int tid = threadIdx.x;
    const int gq = blockIdx.x >> 6;   // which group pair {0,1} or {2,3}
    const int gn = blockIdx.x & 63;   // neuron slice
    const int gA = 2 * gq, gB = 2 * gq + 1;
    const int bA = gA * MB, bB = gB * MB;
    const int j0 = gn * NJ;
    const int jp = tid & 3;
    const int bb = (tid >> 2) & 31;
    const int kh = tid >> 7;
    const int jj0 = 2 * jp;
    const unsigned smu = (unsigned)__cvta_generic_to_shared(smem);

    float* WZRf = (float*)(smem + WZR_OFF);
    float* WH2f = (float*)(smem + WH2_OFF);
    u64* wzrx = (u64*)(smem + WZRX_OFF);
    u64* whx  = (u64*)(smem + WHX_OFF);

    // ---- prologue: W_enc into WH2; stage init_state for both groups ----
    for (int idx = tid; idx < 4 * NR; idx += NTH) {
        int p = idx >> 9, k = idx & 511;
        WH2f[p * 2 * WH2_ROWD + 2 * k]     = W_enc[(size_t)(j0 + 2 * p) * NR + k];
        WH2f[p * 2 * WH2_ROWD + 2 * k + 1] = W_enc[(size_t)(j0 + 2 * p + 1) * NR + k];
    }
    issue_stage(init_state, smu + HS0_OFF, x, smu + XT0_OFF, bA, 0, true, tid);
    issue_stage(init_state, smu + HS1_OFF, x, smu + XT1_OFF, bB, 0, true, tid);
    CP_WAIT(0);
    __syncthreads();

    if (tid < 128) {  // owners: full-512 encoder dot for both groups
        const ulonglong2* wrow =
            (const ulonglong2*)(smem + WH2_OFF) + jp * (WH2_ROWD / 2);
#pragma unroll
        for (int g = 0; g < 2; g++) {
            const float4* hr = (const float4*)(
                smem + (g ? HS1_OFF : HS0_OFF) + bb * HS_STRIDE);
            u64 d0 = 0ull, d1 = 0ull;
#pragma unroll 8
            for (int k4 = 0; k4 < 128; k4++) {
                float4 v = hr[k4];
                ulonglong2 wa = wrow[2 * k4];
                ulonglong2 wb = wrow[2 * k4 + 1];
                d0 = ffma2(pack2(v.x, v.x), wa.x, d0);
                d1 = ffma2(pack2(v.y, v.y), wa.y, d1);
                d0 = ffma2(pack2(v.z, v.z), wb.x, d0);
                d1 = ffma2(pack2(v.w, v.w), wb.y, d1);
            }
            d0 = addf2(d0, d1);
            int b0g = g ? bB : bA;
            *(float2*)&g_h[(size_t)(b0g + bb) * NR + j0 + jj0] = unpack2(d0);
        }
    }
    __syncthreads();

    // ---- stationary recurrent weights ----
    for (int idx = tid; idx < NJ * NR; idx += NTH) {
        int jj = idx >> 9, k = idx & 511;
        int base = k * 16 + 4 * (jj >> 1) + 2 * (jj & 1);
        WZRf[base]     = W_uz[(size_t)(j0 + jj) * NR + k];
        WZRf[base + 1] = W_ur[(size_t)(j0 + jj) * NR + k];
    }
    for (int idx = tid; idx < 4 * NR; idx += NTH) {
        int p = idx >> 9, k = idx & 511;
        WH2f[p * 2 * WH2_ROWD + 2 * k]     = W_uh[(size_t)(j0 + 2 * p) * NR + k];
        WH2f[p * 2 * WH2_ROWD + 2 * k + 1] = W_uh[(size_t)(j0 + 2 * p + 1) * NR + k];
    }
    if (tid < NJ) {
        wzrx[tid]     = pack2(W_wz[(j0 + tid) * 2 + 0], W_wr[(j0 + tid) * 2 + 0]);
        wzrx[8 + tid] = pack2(W_wz[(j0 + tid) * 2 + 1], W_wr[(j0 + tid) * 2 + 1]);
    }
    if (tid < 4) {
        whx[tid]     = pack2(W_wh[(j0 + 2 * tid) * 2 + 0], W_wh[(j0 + 2 * tid + 1) * 2 + 0]);
        whx[4 + tid] = pack2(W_wh[(j0 + 2 * tid) * 2 + 1], W_wh[(j0 + 2 * tid + 1) * 2 + 1]);
    }
    __syncthreads();

    unsigned ev = 1;
    bar_arrive(gA, gn, tid, ev);
    bar_arrive(gB, gn, tid, ev);
    bar_wait(gA, gn, tid, ev);
    issue_stage(g_h, smu + HS0_OFF, x, smu + XT0_OFF, bA, 0, false, tid);
    bar_wait(gB, gn, tid, ev);
    issue_stage(g_h, smu + HS1_OFF, x, smu + XT1_OFF, bB, 0, false, tid);
    CP_WAIT(1);
    __syncthreads();  // HS0 ready; HS1 pending(1)

    float zA0, zA1, zB0, zB1;
    float2 hownA, hownB;

    for (int t = 0; t < TT; t++) {
        const unsigned e1 = ev + 1, e2 = ev + 2;
        // --- phase 1 A ---
        phase1(smem, HS0_OFF, XT0_OFF, bA, j0, tid, jp, bb, kh, zA0, zA1, hownA);
        bar_arrive(gA, gn, tid, e1);
        CP_WAIT(0);
        __syncthreads();  // HS1 (h_B) ready
        // --- phase 1 B ---
        phase1(smem, HS1_OFF, XT1_OFF, bB, j0, tid, jp, bb, kh, zB0, zB1, hownB);
        bar_arrive(gB, gn, tid, e1);
        // --- exchange rh ---
        bar_wait(gA, gn, tid, e1);
        issue_stage(g_rh, smu + HS0_OFF, x, smu + XT0_OFF, bA, 0, false, tid);
        bar_wait(gB, gn, tid, e1);
        issue_stage(g_rh, smu + HS1_OFF, x, smu + XT1_OFF, bB, 0, false, tid);
        CP_WAIT(1);
        __syncthreads();  // HS0 = rh_A
        // --- phase 2 A ---
        phase2(smem, HS0_OFF, XT0_OFF, bA, j0, tid, jp, bb, kh, t, zA0, zA1,
               hownA, out_h);
        bar_arrive(gA, gn, tid, e2);
        CP_WAIT(0);
        __syncthreads();  // HS1 = rh_B
        // --- phase 2 B ---
        phase2(smem, HS1_OFF, XT1_OFF, bB, j0, tid, jp, bb, kh, t, zB0, zB1,
               hownB, out_h);
        bar_arrive(gB, gn, tid, e2);
        // --- exchange h(t+1) ---
        bar_wait(gA, gn, tid, e2);
        issue_stage(g_h, smu + HS0_OFF, x, smu + XT0_OFF, bA, t + 1,
                    t + 1 < TT, tid);
        bar_wait(gB, gn, tid, e2);
        issue_stage(g_h, smu + HS1_OFF, x, smu + XT1_OFF, bB, t + 1,
                    t + 1 < TT, tid);
        CP_WAIT(1);
        __syncthreads();  // HS0 ready for next iter
        ev += 2;
    }
    CP_WAIT(0);
    __syncthreads();
}

// ---------------- decoder: y = h @ W_dec^T  (f32x2 tiled GEMM) ----------------
__global__ void __launch_bounds__(256)
decoder_kernel(const float* __restrict__ h, const float* __restrict__ W,
               float* __restrict__ y) {
    __shared__ float HT[32 * 132];
    __shared__ float WT[32 * 68];
    const int tid = threadIdx.x;
    const int bt0 = blockIdx.x * 128;
    const int o0  = blockIdx.y * 64;
    const int rg = tid & 15;
    const int cg = tid >> 4;
    const int col0 = cg * 4;
    const int lrow = tid >> 1, lkh = (tid & 1) * 16;
    const int lcol = tid >> 2, lkw = (tid & 3) * 8;

    u64 acc[4][4];
#pragma unroll
    for (int i = 0; i < 4; i++)
#pragma unroll
        for (int c = 0; c < 4; c++) acc[i][c] = 0ull;

    for (int k0 = 0; k0 < NR; k0 += 32) {
        __syncthreads();
        const float4* hsrc =
            (const float4*)(h + (size_t)(bt0 + lrow) * NR + k0 + lkh);
#pragma unroll
        for (int j = 0; j < 4; j++) {
            float4 v = hsrc[j];
            int kk = lkh + 4 * j;
            HT[(kk + 0) * 132 + lrow] = v.x;
            HT[(kk + 1) * 132 + lrow] = v.y;
            HT[(kk + 2) * 132 + lrow] = v.z;
            HT[(kk + 3) * 132 + lrow] = v.w;
        }
        const float4* wsrc =
            (const float4*)(W + (size_t)(o0 + lcol) * NR + k0 + lkw);
#pragma unroll
        for (int j = 0; j < 2; j++) {
            float4 v = wsrc[j];
            int kk = lkw + 4 * j;
            WT[(kk + 0) * 68 + lcol] = v.x;
            WT[(kk + 1) * 68 + lcol] = v.y;
            WT[(kk + 2) * 68 + lcol] = v.z;
            WT[(kk + 3) * 68 + lcol] = v.w;
        }
        __syncthreads();
#pragma unroll 4
        for (int k = 0; k < 32; k++) {
            const u64* HTd = (const u64*)(HT + k * 132);
            u64 h0 = HTd[rg];
            u64 h1 = HTd[rg + 16];
            u64 h2 = HTd[rg + 32];
            u64 h3 = HTd[rg + 48];
            float4 wv = *(const float4*)(WT + k * 68 + col0);
            u64 w0 = pack2(wv.x, wv.x);
            u64 w1 = pack2(wv.y, wv.y);
            u64 w2 = pack2(wv.z, wv.z);
            u64 w3 = pack2(wv.w, wv.w);
            acc[0][0] = ffma2(h0, w0, acc[0][0]);
            acc[0][1] = ffma2(h0, w1, acc[0][1]);
            acc[0][2] = ffma2(h0, w2, acc[0][2]);
            acc[0][3] = ffma2(h0, w3, acc[0][3]);
            acc[1][0] = ffma2(h1, w0, acc[1][0]);
            acc[1][1] = ffma2(h1, w1, acc[1][1]);
            acc[1][2] = ffma2(h1, w2, acc[1][2]);
            acc[1][3] = ffma2(h1, w3, acc[1][3]);
            acc[2][0] = ffma2(h2, w0, acc[2][0]);
            acc[2][1] = ffma2(h2, w1, acc[2][1]);
            acc[2][2] = ffma2(h2, w2, acc[2][2]);
            acc[2][3] = ffma2(h2, w3, acc[2][3]);
            acc[3][0] = ffma2(h3, w0, acc[3][0]);
            acc[3][1] = ffma2(h3, w1, acc[3][1]);
            acc[3][2] = ffma2(h3, w2, acc[3][2]);
            acc[3][3] = ffma2(h3, w3, acc[3][3]);
        }
    }
#pragma unroll
    for (int i = 0; i < 4; i++) {
        int r = 2 * rg + 32 * i;
        float2 p0 = unpack2(acc[i][0]);
        float2 p1 = unpack2(acc[i][1]);
        float2 p2 = unpack2(acc[i][2]);
        float2 p3 = unpack2(acc[i][3]);
        float4 ra = make_float4(p0.x, p1.x, p2.x, p3.x);
        float4 rb = make_float4(p0.y, p1.y, p2.y, p3.y);
        *(float4*)(y + (size_t)(bt0 + r) * NOUT + o0 + col0) = ra;
        *(float4*)(y + (size_t)(bt0 + r + 1) * NOUT + o0 + col0) = rb;
    }
}

// ---------------- launch -------------------------------------------------------
extern "C" void kernel_launch(void* const* d_in, const int* in_sizes, int n_in,
                              void* d_out, int out_size) {
    const float* x          = (const float*)d_in[0];
    const float* init_state = (const float*)d_in[1];
    const float* W_enc      = (const float*)d_in[2];
    const float* W_wz       = (const float*)d_in[3];
    const float* W_uz       = (const float*)d_in[4];
    const float* W_wr       = (const float*)d_in[5];
    const float* W_ur       = (const float*)d_in[6];
    const float* W_wh       = (const float*)d_in[7];
    const float* W_uh       = (const float*)d_in[8];
    const float* W_dec      = (const float*)d_in[9];
    float* out = (float*)d_out;

    cudaFuncSetAttribute(rnn_persistent,
                         cudaFuncAttributeMaxDynamicSharedMemorySize, SMEM_TOTAL);

    init_bar_kernel<<<1, 256>>>();
    rnn_persistent<<<128, NTH, SMEM_TOTAL>>>(
        x, init_state, W_enc, W_wz, W_uz, W_wr, W_ur, W_wh, W_uh, out);

    size_t hN = (size_t)BN * TT * NR;
    if ((size_t)out_size >= 2 * hN) {
        dim3 grid((BN * TT) / 128, NOUT / 64);
        decoder_kernel<<<grid, 256>>>(out, W_dec, out + hN);
    }
}

// round 9
// speedup vs baseline: 1.0749x; 1.0749x over previous
#include <cuda_runtime.h>
#include <cstdint>

// Problem dims
#define BN    128
#define TT    512
#define NR    512
#define NOUT  512
#define PM    4     // batch groups
#define PN    32    // neuron-slice CTAs per group
#define MB    32    // batch rows per group
#define NJ    16    // neurons per CTA
#define NTH   256
#define DT_TAU 0.2f

typedef unsigned long long u64;

// ---------------- global scratch ---------------------------------------------
__device__ float g_h[BN * NR];
__device__ float g_rh[BN * NR];
__device__ unsigned g_arr[PM][PN];

// ---------------- f32x2 helpers ----------------------------------------------
__device__ __forceinline__ u64 ffma2(u64 a, u64 b, u64 c) {
    u64 d;
    asm("fma.rn.f32x2 %0, %1, %2, %3;" : "=l"(d) : "l"(a), "l"(b), "l"(c));
    return d;
}
__device__ __forceinline__ u64 addf2(u64 a, u64 b) {
    u64 d;
    asm("add.rn.f32x2 %0, %1, %2;" : "=l"(d) : "l"(a), "l"(b));
    return d;
}
__device__ __forceinline__ u64 pack2(float lo, float hi) {
    u64 d;
    asm("mov.b64 %0, {%1, %2};" : "=l"(d) : "f"(lo), "f"(hi));
    return d;
}
__device__ __forceinline__ float2 unpack2(u64 d) {
    float2 r;
    asm("mov.b64 {%0, %1}, %2;" : "=f"(r.x), "=f"(r.y) : "l"(d));
    return r;
}
__device__ __forceinline__ unsigned ld_acq(const unsigned* p) {
    unsigned v;
    asm volatile("ld.acquire.gpu.u32 %0, [%1];" : "=r"(v) : "l"(p) : "memory");
    return v;
}
__device__ __forceinline__ void st_rel(unsigned* p, unsigned v) {
    asm volatile("st.release.gpu.u32 [%0], %1;" :: "l"(p), "r"(v) : "memory");
}
__device__ __forceinline__ void cp16(unsigned dst, const void* src) {
    asm volatile("cp.async.cg.shared.global [%0], [%1], 16;"
                 :: "r"(dst), "l"(src) : "memory");
}
__device__ __forceinline__ void cp8(unsigned dst, const void* src) {
    asm volatile("cp.async.ca.shared.global [%0], [%1], 8;"
                 :: "r"(dst), "l"(src) : "memory");
}
#define CP_COMMIT() asm volatile("cp.async.commit_group;" ::: "memory")
#define CP_WAIT(N)  asm volatile("cp.async.wait_group %0;" :: "n"(N) : "memory")

// ---------------- SMEM layout (byte offsets; same as R5) ----------------------
#define WZR_OFF   0
#define WH2_OFF   65536
#define WH2_ROWD  514
#define HS_OFF    (WH2_OFF + 8 * WH2_ROWD * 8)            // 98432
#define HS_STRIDE 2064
#define XT_OFF    (HS_OFF + MB * HS_STRIDE)               // 164480
#define WZRX_OFF  (XT_OFF + 256)                          // 164736
#define WHX_OFF   (WZRX_OFF + 256)                        // 164992
#define SMEM_TOTAL (WHX_OFF + 128)                        // 165120

// ---------------- 1-hop group barrier (all CTAs scan all flags) ---------------
__device__ __forceinline__ void bar_sync(int gm, int gn, int tid, unsigned tgt) {
    __syncthreads();                       // all CTA threads' stores done
    if (tid == 0) st_rel(&g_arr[gm][gn], tgt);
    if (tid < 32) {
        unsigned v;
        do { v = ld_acq(&g_arr[gm][tid]); }
        while (!__all_sync(0xffffffffu, v >= tgt));
    }
    __syncthreads();
}

__global__ void init_bar_kernel() {
    int i = threadIdx.x;
    if (i < PM * PN) ((unsigned*)g_arr)[i] = 0u;
}

// ---------------- chunked async staging: 32 rows x 512 floats ----------------
// 4 commit groups; chunk c covers k in [128c, 128c+128). x rides chunk 0.
__device__ __forceinline__ void issue_chunks(const float* __restrict__ src,
                                             unsigned hs_u32,
                                             const float* __restrict__ xsrc,
                                             unsigned xt_u32, int b0, int t,
                                             bool do_x, int tid) {
    int row = tid >> 3, c0 = tid & 7;
    const float4* s = (const float4*)(src + (size_t)(b0 + row) * NR) + c0;
    unsigned d = hs_u32 + row * HS_STRIDE + c0 * 16;
#pragma unroll
    for (int c = 0; c < 4; c++) {
#pragma unroll
        for (int i = 4 * c; i < 4 * c + 4; i++) cp16(d + i * 128, s + 8 * i);
        if (c == 0 && do_x && tid < 32)
            cp8(xt_u32 + tid * 8, xsrc + ((size_t)(b0 + tid) * TT + t) * 2);
        CP_COMMIT();
    }
}

// ---------------- full dot over K=512 (prologue h0) ---------------------------
__device__ __forceinline__ u64 dot512(const float4* __restrict__ hr4,
                                      const ulonglong2* __restrict__ w,
                                      u64 init) {
    u64 u = init, ub = 0ull;
#pragma unroll 8
    for (int k4 = 0; k4 < 128; k4++) {
        float4 v = hr4[k4];
        ulonglong2 wa = w[2 * k4];
        ulonglong2 wb = w[2 * k4 + 1];
        u  = ffma2(pack2(v.x, v.x), wa.x, u);
        ub = ffma2(pack2(v.y, v.y), wa.y, ub);
        u  = ffma2(pack2(v.z, v.z), wb.x, u);
        ub = ffma2(pack2(v.w, v.w), wb.y, ub);
    }
    return addf2(u, ub);
}

// ---------------- phase sub-ranges (32 k4 iters = 128 k) ----------------------
__device__ __forceinline__ void p1_sub(const char* smem, int jp, int bb, int c,
                                       u64& a0, u64& a1, u64& a0b, u64& a1b) {
    const float4* hr = (const float4*)(smem + HS_OFF + bb * HS_STRIDE);
    const ulonglong2* wz = (const ulonglong2*)(smem + WZR_OFF) + jp;
#pragma unroll 8
    for (int i = 0; i < 32; i++) {
        int k4 = 32 * c + i;
        float4 hv = hr[k4];
        u64 hx = pack2(hv.x, hv.x);
        ulonglong2 w0 = wz[(4 * k4 + 0) * 8];
        a0  = ffma2(hx, w0.x, a0);  a1  = ffma2(hx, w0.y, a1);
        u64 hy = pack2(hv.y, hv.y);
        ulonglong2 w1 = wz[(4 * k4 + 1) * 8];
        a0b = ffma2(hy, w1.x, a0b); a1b = ffma2(hy, w1.y, a1b);
        u64 hz = pack2(hv.z, hv.z);
        ulonglong2 w2 = wz[(4 * k4 + 2) * 8];
        a0  = ffma2(hz, w2.x, a0);  a1  = ffma2(hz, w2.y, a1);
        u64 hw = pack2(hv.w, hv.w);
        ulonglong2 w3 = wz[(4 * k4 + 3) * 8];
        a0b = ffma2(hw, w3.x, a0b); a1b = ffma2(hw, w3.y, a1b);
    }
}

__device__ __forceinline__ void p2_sub(const char* smem, int jp, int bb, int c,
                                       u64& uu, u64& ub) {
    const float4* hr = (const float4*)(smem + HS_OFF + bb * HS_STRIDE);
    const ulonglong2* w =
        (const ulonglong2*)(smem + WH2_OFF) + jp * (WH2_ROWD / 2);
#pragma unroll 8
    for (int i = 0; i < 32; i++) {
        int k4 = 32 * c + i;
        float4 v = hr[k4];
        ulonglong2 wa = w[2 * k4];
        ulonglong2 wb = w[2 * k4 + 1];
        uu = ffma2(pack2(v.x, v.x), wa.x, uu);
        ub = ffma2(pack2(v.y, v.y), wa.y, ub);
        uu = ffma2(pack2(v.z, v.z), wb.x, uu);
        ub = ffma2(pack2(v.w, v.w), wb.y, ub);
    }
}

// ---------------- persistent recurrent kernel ---------------------------------
__global__ void __launch_bounds__(NTH, 1)
rnn_persistent(const float* __restrict__ x, const float* __restrict__ init_state,
               const float* __restrict__ W_enc, const float* __restrict__ W_wz,
               const float* __restrict__ W_uz, const float* __restrict__ W_wr,
               const float* __restrict__ W_ur, const float* __restrict__ W_wh,
               const float* __restrict__ W_uh, float* __restrict__ out_h) {
    extern __shared__ char smem[];
    const int tid = threadIdx.x;
    const int gm = blockIdx.x & 3;
    const int gn = blockIdx.x >> 2;
    const int b0 = gm * MB;
    const int j0 = gn * NJ;
    // quartet retile: warp covers 4 jp x 8 bb; thread-half selects jp quartet
    const int jp = (tid & 3) + 4 * (tid >> 7);
    const int bb = (tid >> 2) & 31;
    const int jj0 = 2 * jp;
    const unsigned smu = (unsigned)__cvta_generic_to_shared(smem);
    unsigned ev = 0;

    float* WZRf = (float*)(smem + WZR_OFF);
    float* WH2f = (float*)(smem + WH2_OFF);
    const ulonglong2* WHrow =
        (const ulonglong2*)(smem + WH2_OFF) + jp * (WH2_ROWD / 2);
    u64* wzrx = (u64*)(smem + WZRX_OFF);
    u64* whx  = (u64*)(smem + WHX_OFF);
    float2* xts = (float2*)(smem + XT_OFF);
    const float4* hrow4 = (const float4*)(smem + HS_OFF + bb * HS_STRIDE);

    // ---- prologue: W_enc slice into WH2 layout; stage init_state ----
    issue_chunks(init_state, smu + HS_OFF, x, smu + XT_OFF, b0, 0, false, tid);
    for (int idx = tid; idx < 8 * NR; idx += NTH) {
        int p = idx >> 9, k = idx & 511;
        WH2f[p * 2 * WH2_ROWD + 2 * k]     = W_enc[(size_t)(j0 + 2 * p) * NR + k];
        WH2f[p * 2 * WH2_ROWD + 2 * k + 1] = W_enc[(size_t)(j0 + 2 * p + 1) * NR + k];
    }
    CP_WAIT(0);
    __syncthreads();
    {
        u64 h0d = dot512(hrow4, WHrow, 0ull);
        *(float2*)&g_h[(size_t)(b0 + bb) * NR + j0 + jj0] = unpack2(h0d);
    }
    __syncthreads();  // all reads of WH2/HS done before overwrite

    // ---- stationary recurrent weights (same layout as R5) ----
    for (int idx = tid; idx < NJ * NR; idx += NTH) {
        int jj = idx >> 9, k = idx & 511;
        WZRf[k * 32 + 2 * jj]     = W_uz[(size_t)(j0 + jj) * NR + k];
        WZRf[k * 32 + 2 * jj + 1] = W_ur[(size_t)(j0 + jj) * NR + k];
    }
    for (int idx = tid; idx < 8 * NR; idx += NTH) {
        int p = idx >> 9, k = idx & 511;
        WH2f[p * 2 * WH2_ROWD + 2 * k]     = W_uh[(size_t)(j0 + 2 * p) * NR + k];
        WH2f[p * 2 * WH2_ROWD + 2 * k + 1] = W_uh[(size_t)(j0 + 2 * p + 1) * NR + k];
    }
    if (tid < NJ) {
        wzrx[tid]      = pack2(W_wz[(j0 + tid) * 2 + 0], W_wr[(j0 + tid) * 2 + 0]);
        wzrx[16 + tid] = pack2(W_wz[(j0 + tid) * 2 + 1], W_wr[(j0 + tid) * 2 + 1]);
    }
    if (tid < 8) {
        whx[tid]     = pack2(W_wh[(j0 + 2 * tid) * 2 + 0], W_wh[(j0 + 2 * tid + 1) * 2 + 0]);
        whx[8 + tid] = pack2(W_wh[(j0 + 2 * tid) * 2 + 1], W_wh[(j0 + 2 * tid + 1) * 2 + 1]);
    }
    bar_sync(gm, gn, tid, ++ev);  // h0 visible group-wide
    issue_chunks(g_h, smu + HS_OFF, x, smu + XT_OFF, b0, 0, true, tid);

    u64 x0p = 0ull, x1p = 0ull;

    for (int t = 0; t < TT; t++) {
        // ---------------- phase 1: z, r, r*h (4 pipelined chunks) ----------
        u64 a0, a1, a0b = 0ull, a1b = 0ull;
        CP_WAIT(3);
        __syncthreads();
        {
            float2 xt = xts[bb];
            x0p = pack2(xt.x, xt.x);
            x1p = pack2(xt.y, xt.y);
            a0 = ffma2(x0p, wzrx[jj0],     ffma2(x1p, wzrx[16 + jj0],     0ull));
            a1 = ffma2(x0p, wzrx[jj0 + 1], ffma2(x1p, wzrx[16 + jj0 + 1], 0ull));
        }
        p1_sub(smem, jp, bb, 0, a0, a1, a0b, a1b);
        CP_WAIT(2); __syncthreads();
        p1_sub(smem, jp, bb, 1, a0, a1, a0b, a1b);
        CP_WAIT(1); __syncthreads();
        p1_sub(smem, jp, bb, 2, a0, a1, a0b, a1b);
        CP_WAIT(0); __syncthreads();
        p1_sub(smem, jp, bb, 3, a0, a1, a0b, a1b);
        a0 = addf2(a0, a0b);
        a1 = addf2(a1, a1b);
        float2 zr0 = unpack2(a0), zr1 = unpack2(a1);
        float z0 = 1.f / (1.f + __expf(-zr0.x));
        float r0 = 1.f / (1.f + __expf(-zr0.y));
        float z1 = 1.f / (1.f + __expf(-zr1.x));
        float r1 = 1.f / (1.f + __expf(-zr1.y));
        float2 hown = *(const float2*)(smem + HS_OFF + bb * HS_STRIDE +
                                       (size_t)(j0 + jj0) * 4);
        float2 rh = make_float2(r0 * hown.x, r1 * hown.y);
        *(float2*)&g_rh[(size_t)(b0 + bb) * NR + j0 + jj0] = rh;

        bar_sync(gm, gn, tid, ++ev);  // rh visible group-wide
        issue_chunks(g_rh, smu + HS_OFF, x, smu + XT_OFF, b0, 0, false, tid);

        // ---------------- phase 2: u, tanh, h update -----------------------
        u64 uu, ub = 0ull;
        CP_WAIT(3); __syncthreads();
        uu = ffma2(x0p, whx[jp], ffma2(x1p, whx[8 + jp], 0ull));
        p2_sub(smem, jp, bb, 0, uu, ub);
        CP_WAIT(2); __syncthreads();
        p2_sub(smem, jp, bb, 1, uu, ub);
        CP_WAIT(1); __syncthreads();
        p2_sub(smem, jp, bb, 2, uu, ub);
        CP_WAIT(0); __syncthreads();
        p2_sub(smem, jp, bb, 3, uu, ub);
        uu = addf2(uu, ub);
        float2 uf = unpack2(uu);
        float th0 = tanhf(uf.x), th1 = tanhf(uf.y);
        float2 hn;
        hn.x = hown.x + DT_TAU * (z0 - 1.f) * (hown.x - th0);
        hn.y = hown.y + DT_TAU * (z1 - 1.f) * (hown.y - th1);
        *(float2*)&g_h[(size_t)(b0 + bb) * NR + j0 + jj0] = hn;
        *(float2*)&out_h[((size_t)(b0 + bb) * TT + t) * NR + j0 + jj0] = hn;

        bar_sync(gm, gn, tid, ++ev);  // h(t+1) visible group-wide
        if (t + 1 < TT)
            issue_chunks(g_h, smu + HS_OFF, x, smu + XT_OFF, b0, t + 1, true, tid);
    }
}

// ---------------- decoder: y = h @ W_dec^T  (f32x2 tiled GEMM) ----------------
__global__ void __launch_bounds__(256)
decoder_kernel(const float* __restrict__ h, const float* __restrict__ W,
               float* __restrict__ y) {
    __shared__ float HT[32 * 132];
    __shared__ float WT[32 * 68];
    const int tid = threadIdx.x;
    const int bt0 = blockIdx.x * 128;
    const int o0  = blockIdx.y * 64;
    const int rg = tid & 15;
    const int cg = tid >> 4;
    const int col0 = cg * 4;
    const int lrow = tid >> 1, lkh = (tid & 1) * 16;
    const int lcol = tid >> 2, lkw = (tid & 3) * 8;

    u64 acc[4][4];
#pragma unroll
    for (int i = 0; i < 4; i++)
#pragma unroll
        for (int c = 0; c < 4; c++) acc[i][c] = 0ull;

    for (int k0 = 0; k0 < NR; k0 += 32) {
        __syncthreads();
        const float4* hsrc =
            (const float4*)(h + (size_t)(bt0 + lrow) * NR + k0 + lkh);
#pragma unroll
        for (int j = 0; j < 4; j++) {
            float4 v = hsrc[j];
            int kk = lkh + 4 * j;
            HT[(kk + 0) * 132 + lrow] = v.x;
            HT[(kk + 1) * 132 + lrow] = v.y;
            HT[(kk + 2) * 132 + lrow] = v.z;
            HT[(kk + 3) * 132 + lrow] = v.w;
        }
        const float4* wsrc =
            (const float4*)(W + (size_t)(o0 + lcol) * NR + k0 + lkw);
#pragma unroll
        for (int j = 0; j < 2; j++) {
            float4 v = wsrc[j];
            int kk = lkw + 4 * j;
            WT[(kk + 0) * 68 + lcol] = v.x;
            WT[(kk + 1) * 68 + lcol] = v.y;
            WT[(kk + 2) * 68 + lcol] = v.z;
            WT[(kk + 3) * 68 + lcol] = v.w;
        }
        __syncthreads();
#pragma unroll 4
        for (int k = 0; k < 32; k++) {
            const u64* HTd = (const u64*)(HT + k * 132);
            u64 h0 = HTd[rg];
            u64 h1 = HTd[rg + 16];
            u64 h2 = HTd[rg + 32];
            u64 h3 = HTd[rg + 48];
            float4 wv = *(const float4*)(WT + k * 68 + col0);
            u64 w0 = pack2(wv.x, wv.x);
            u64 w1 = pack2(wv.y, wv.y);
            u64 w2 = pack2(wv.z, wv.z);
            u64 w3 = pack2(wv.w, wv.w);
            acc[0][0] = ffma2(h0, w0, acc[0][0]);
            acc[0][1] = ffma2(h0, w1, acc[0][1]);
            acc[0][2] = ffma2(h0, w2, acc[0][2]);
            acc[0][3] = ffma2(h0, w3, acc[0][3]);
            acc[1][0] = ffma2(h1, w0, acc[1][0]);
            acc[1][1] = ffma2(h1, w1, acc[1][1]);
            acc[1][2] = ffma2(h1, w2, acc[1][2]);
            acc[1][3] = ffma2(h1, w3, acc[1][3]);
            acc[2][0] = ffma2(h2, w0, acc[2][0]);
            acc[2][1] = ffma2(h2, w1, acc[2][1]);
            acc[2][2] = ffma2(h2, w2, acc[2][2]);
            acc[2][3] = ffma2(h2, w3, acc[2][3]);
            acc[3][0] = ffma2(h3, w0, acc[3][0]);
            acc[3][1] = ffma2(h3, w1, acc[3][1]);
            acc[3][2] = ffma2(h3, w2, acc[3][2]);
            acc[3][3] = ffma2(h3, w3, acc[3][3]);
        }
    }
#pragma unroll
    for (int i = 0; i < 4; i++) {
        int r = 2 * rg + 32 * i;
        float2 p0 = unpack2(acc[i][0]);
        float2 p1 = unpack2(acc[i][1]);
        float2 p2 = unpack2(acc[i][2]);
        float2 p3 = unpack2(acc[i][3]);
        float4 ra = make_float4(p0.x, p1.x, p2.x, p3.x);
        float4 rb = make_float4(p0.y, p1.y, p2.y, p3.y);
        *(float4*)(y + (size_t)(bt0 + r) * NOUT + o0 + col0) = ra;
        *(float4*)(y + (size_t)(bt0 + r + 1) * NOUT + o0 + col0) = rb;
    }
}

// ---------------- launch -------------------------------------------------------
extern "C" void kernel_launch(void* const* d_in, const int* in_sizes, int n_in,
                              void* d_out, int out_size) {
    const float* x          = (const float*)d_in[0];
    const float* init_state = (const float*)d_in[1];
    const float* W_enc      = (const float*)d_in[2];
    const float* W_wz       = (const float*)d_in[3];
    const float* W_uz       = (const float*)d_in[4];
    const float* W_wr       = (const float*)d_in[5];
    const float* W_ur       = (const float*)d_in[6];
    const float* W_wh       = (const float*)d_in[7];
    const float* W_uh       = (const float*)d_in[8];
    const float* W_dec      = (const float*)d_in[9];
    float* out = (float*)d_out;

    cudaFuncSetAttribute(rnn_persistent,
                         cudaFuncAttributeMaxDynamicSharedMemorySize, SMEM_TOTAL);

    init_bar_kernel<<<1, 256>>>();
    rnn_persistent<<<PM * PN, NTH, SMEM_TOTAL>>>(
        x, init_state, W_enc, W_wz, W_uz, W_wr, W_ur, W_wh, W_uh, out);

    size_t hN = (size_t)BN * TT * NR;
    if ((size_t)out_size >= 2 * hN) {
        dim3 grid((BN * TT) / 128, NOUT / 64);
        decoder_kernel<<<grid, 256>>>(out, W_dec, out + hN);
    }
}

// round 10
// speedup vs baseline: 1.2237x; 1.1385x over previous
#include <cuda_runtime.h>
#include <cstdint>

// Problem dims
#define BN    128
#define TT    512
#define NR    512
#define NOUT  512
#define PM    4     // batch groups
#define PN    32    // neuron-slice CTAs per group
#define MB    32    // batch rows per group
#define NJ    16    // neurons per CTA
#define NTH   256
#define DT_TAU 0.2f

typedef unsigned long long u64;

// ---------------- global scratch ---------------------------------------------
__device__ float g_h[BN * NR];
__device__ float g_rh[BN * NR];
__device__ unsigned g_cnt[PM];
__device__ volatile unsigned g_gen[PM];

// ---------------- f32x2 helpers ----------------------------------------------
__device__ __forceinline__ u64 ffma2(u64 a, u64 b, u64 c) {
    u64 d;
    asm("fma.rn.f32x2 %0, %1, %2, %3;" : "=l"(d) : "l"(a), "l"(b), "l"(c));
    return d;
}
__device__ __forceinline__ u64 addf2(u64 a, u64 b) {
    u64 d;
    asm("add.rn.f32x2 %0, %1, %2;" : "=l"(d) : "l"(a), "l"(b));
    return d;
}
__device__ __forceinline__ u64 pack2(float lo, float hi) {
    u64 d;
    asm("mov.b64 %0, {%1, %2};" : "=l"(d) : "f"(lo), "f"(hi));
    return d;
}
__device__ __forceinline__ float2 unpack2(u64 d) {
    float2 r;
    asm("mov.b64 {%0, %1}, %2;" : "=f"(r.x), "=f"(r.y) : "l"(d));
    return r;
}
__device__ __forceinline__ void cp16(unsigned dst, const void* src) {
    asm volatile("cp.async.cg.shared.global [%0], [%1], 16;"
                 :: "r"(dst), "l"(src) : "memory");
}
__device__ __forceinline__ void cp8(unsigned dst, const void* src) {
    asm volatile("cp.async.ca.shared.global [%0], [%1], 8;"
                 :: "r"(dst), "l"(src) : "memory");
}
#define CP_COMMIT() asm volatile("cp.async.commit_group;" ::: "memory")
#define CP_WAIT0()  asm volatile("cp.async.wait_group 0;" ::: "memory")

// ---------------- SMEM layout (byte offsets; identical to R5) -----------------
#define WZR_OFF   0
#define WH2_OFF   65536
#define WH2_ROWD  514
#define HS_OFF    (WH2_OFF + 8 * WH2_ROWD * 8)            // 98432
#define HS_STRIDE 2064
#define XT_OFF    (HS_OFF + MB * HS_STRIDE)               // 164480
#define WZRX_OFF  (XT_OFF + 256)                          // 164736
#define WHX_OFF   (WZRX_OFF + 256)                        // 164992
#define SMEM_TOTAL (WHX_OFF + 128)                        // 165120

// ---------------- group barrier (R5 atomic version, launch-reset) -------------
__device__ __forceinline__ void group_barrier(int g, unsigned& idx) {
    __syncthreads();
    if (threadIdx.x == 0) {
        __threadfence();  // release: publish this CTA's global stores
        unsigned old = atomicAdd(&g_cnt[g], 1u);
        if (old == idx * (unsigned)PN + (PN - 1)) {
            __threadfence();
            g_gen[g] = idx + 1u;
        } else {
            while (g_gen[g] < idx + 1u) {}
            __threadfence();  // acquire
        }
    }
    __syncthreads();
    idx++;
}

// Runs LAST each replay: leaves barrier state zeroed for the next replay.
__global__ void reset_bar_kernel() {
    int i = threadIdx.x;
    if (i < PM) { g_cnt[i] = 0u; g_gen[i] = 0u; }
}

// ---------------- async staging: 32 rows x 512 floats -> HS (one group) ------
__device__ __forceinline__ void issue_stage(const float* __restrict__ src,
                                            unsigned hs_u32,
                                            const float* __restrict__ xsrc,
                                            unsigned xt_u32, int b0, int t,
                                            bool do_x, int tid) {
    int row = tid >> 3, c0 = tid & 7;
    const float4* s = (const float4*)(src + (size_t)(b0 + row) * NR) + c0;
    unsigned d = hs_u32 + row * HS_STRIDE + c0 * 16;
#pragma unroll
    for (int i = 0; i < 16; i++) cp16(d + i * 128, s + 8 * i);
    if (do_x && tid < 32)
        cp8(xt_u32 + tid * 8, xsrc + ((size_t)(b0 + tid) * TT + t) * 2);
    CP_COMMIT();
}

// dot over K=512 with WH2-layout weights (per-jp row of packed pairs)
__device__ __forceinline__ u64 dot512(const float4* __restrict__ hr4,
                                      const ulonglong2* __restrict__ w,
                                      u64 init) {
    u64 u = init, ub = 0ull;
#pragma unroll 8
    for (int k4 = 0; k4 < 128; k4++) {
        float4 v = hr4[k4];
        ulonglong2 wa = w[2 * k4];
        ulonglong2 wb = w[2 * k4 + 1];
        u  = ffma2(pack2(v.x, v.x), wa.x, u);
        ub = ffma2(pack2(v.y, v.y), wa.y, ub);
        u  = ffma2(pack2(v.z, v.z), wb.x, u);
        ub = ffma2(pack2(v.w, v.w), wb.y, ub);
    }
    return addf2(u, ub);
}

// ---------------- persistent recurrent kernel ---------------------------------
__global__ void __launch_bounds__(NTH, 1)
rnn_persistent(const float* __restrict__ x, const float* __restrict__ init_state,
               const float* __restrict__ W_enc, const float* __restrict__ W_wz,
               const float* __restrict__ W_uz, const float* __restrict__ W_wr,
               const float* __restrict__ W_ur, const float* __restrict__ W_wh,
               const float* __restrict__ W_uh, float* __restrict__ out_h) {
    extern __shared__ char smem[];
    const int tid = threadIdx.x;
    const int gm = blockIdx.x & 3;
    const int gn = blockIdx.x >> 2;
    const int b0 = gm * MB;
    const int j0 = gn * NJ;
    // quartet retile: per-warp jp-diversity = 4 (halves weight crossbar);
    // same (jp, bb) work-set as R5 -> identical arithmetic & rounding.
    const int jp = (tid & 3) + 4 * (tid >> 7);
    const int bb = (tid >> 2) & 31;
    const int jj0 = 2 * jp;
    const unsigned smu = (unsigned)__cvta_generic_to_shared(smem);
    unsigned bidx = 0;

    float* WZRf = (float*)(smem + WZR_OFF);
    float* WH2f = (float*)(smem + WH2_OFF);
    const ulonglong2* WZRd2 = (const ulonglong2*)(smem + WZR_OFF);
    const ulonglong2* WHrow =
        (const ulonglong2*)(smem + WH2_OFF) + jp * (WH2_ROWD / 2);
    u64* wzrx = (u64*)(smem + WZRX_OFF);
    u64* whx  = (u64*)(smem + WHX_OFF);
    float2* xts = (float2*)(smem + XT_OFF);
    const float4* hrow4 = (const float4*)(smem + HS_OFF + bb * HS_STRIDE);

    // ---- prologue: stage init_state; W_enc slice into WH2 layout ----
    issue_stage(init_state, smu + HS_OFF, x, smu + XT_OFF, b0, 0, false, tid);
    for (int idx = tid; idx < 8 * NR; idx += NTH) {
        int p = idx >> 9, k = idx & 511;
        WH2f[p * 2 * WH2_ROWD + 2 * k]     = W_enc[(size_t)(j0 + 2 * p) * NR + k];
        WH2f[p * 2 * WH2_ROWD + 2 * k + 1] = W_enc[(size_t)(j0 + 2 * p + 1) * NR + k];
    }
    CP_WAIT0();
    __syncthreads();
    {
        u64 h0d = dot512(hrow4, WHrow, 0ull);
        *(float2*)&g_h[(size_t)(b0 + bb) * NR + j0 + jj0] = unpack2(h0d);
    }
    __syncthreads();  // all reads of WH2/HS done before overwrite

    // ---- stationary recurrent weights (R5 layout) ----
    for (int idx = tid; idx < NJ * NR; idx += NTH) {
        int jj = idx >> 9, k = idx & 511;
        WZRf[k * 32 + 2 * jj]     = W_uz[(size_t)(j0 + jj) * NR + k];
        WZRf[k * 32 + 2 * jj + 1] = W_ur[(size_t)(j0 + jj) * NR + k];
    }
    for (int idx = tid; idx < 8 * NR; idx += NTH) {
        int p = idx >> 9, k = idx & 511;
        WH2f[p * 2 * WH2_ROWD + 2 * k]     = W_uh[(size_t)(j0 + 2 * p) * NR + k];
        WH2f[p * 2 * WH2_ROWD + 2 * k + 1] = W_uh[(size_t)(j0 + 2 * p + 1) * NR + k];
    }
    if (tid < NJ) {
        wzrx[tid]      = pack2(W_wz[(j0 + tid) * 2 + 0], W_wr[(j0 + tid) * 2 + 0]);
        wzrx[16 + tid] = pack2(W_wz[(j0 + tid) * 2 + 1], W_wr[(j0 + tid) * 2 + 1]);
    }
    if (tid < 8) {
        whx[tid]     = pack2(W_wh[(j0 + 2 * tid) * 2 + 0], W_wh[(j0 + 2 * tid + 1) * 2 + 0]);
        whx[8 + tid] = pack2(W_wh[(j0 + 2 * tid) * 2 + 1], W_wh[(j0 + 2 * tid + 1) * 2 + 1]);
    }
    group_barrier(gm, bidx);  // h0 visible group-wide
    issue_stage(g_h, smu + HS_OFF, x, smu + XT_OFF, b0, 0, true, tid);

    for (int t = 0; t < TT; t++) {
        // ---------------- phase 1: z, r, r*h ----------------
        CP_WAIT0();
        __syncthreads();
        float2 xt = xts[bb];
        u64 x0p = pack2(xt.x, xt.x), x1p = pack2(xt.y, xt.y);
        u64 a0 = ffma2(x0p, wzrx[jj0],     ffma2(x1p, wzrx[16 + jj0],     0ull));
        u64 a1 = ffma2(x0p, wzrx[jj0 + 1], ffma2(x1p, wzrx[16 + jj0 + 1], 0ull));
        u64 a0b = 0ull, a1b = 0ull;
        const ulonglong2* wz = WZRd2 + jp;
#pragma unroll 8
        for (int k4 = 0; k4 < 128; k4++) {
            float4 hv = hrow4[k4];
            u64 hx = pack2(hv.x, hv.x);
            ulonglong2 w0 = wz[(4 * k4 + 0) * 8];
            a0  = ffma2(hx, w0.x, a0);  a1  = ffma2(hx, w0.y, a1);
            u64 hy = pack2(hv.y, hv.y);
            ulonglong2 w1 = wz[(4 * k4 + 1) * 8];
            a0b = ffma2(hy, w1.x, a0b); a1b = ffma2(hy, w1.y, a1b);
            u64 hz = pack2(hv.z, hv.z);
            ulonglong2 w2 = wz[(4 * k4 + 2) * 8];
            a0  = ffma2(hz, w2.x, a0);  a1  = ffma2(hz, w2.y, a1);
            u64 hw = pack2(hv.w, hv.w);
            ulonglong2 w3 = wz[(4 * k4 + 3) * 8];
            a0b = ffma2(hw, w3.x, a0b); a1b = ffma2(hw, w3.y, a1b);
        }
        a0 = addf2(a0, a0b);
        a1 = addf2(a1, a1b);
        float2 zr0 = unpack2(a0), zr1 = unpack2(a1);
        float z0 = 1.f / (1.f + __expf(-zr0.x));
        float r0 = 1.f / (1.f + __expf(-zr0.y));
        float z1 = 1.f / (1.f + __expf(-zr1.x));
        float r1 = 1.f / (1.f + __expf(-zr1.y));
        float2 hown = *(const float2*)(smem + HS_OFF + bb * HS_STRIDE +
                                       (size_t)(j0 + jj0) * 4);
        float2 rh = make_float2(r0 * hown.x, r1 * hown.y);
        *(float2*)&g_rh[(size_t)(b0 + bb) * NR + j0 + jj0] = rh;

        group_barrier(gm, bidx);  // rh visible group-wide
        issue_stage(g_rh, smu + HS_OFF, x, smu + XT_OFF, b0, 0, false, tid);

        // ---------------- phase 2: u, tanh, h update ----------------
        CP_WAIT0();
        __syncthreads();
        u64 ui = ffma2(x0p, whx[jp], ffma2(x1p, whx[8 + jp], 0ull));
        u64 ud = dot512(hrow4, WHrow, ui);
        float2 uf = unpack2(ud);
        float th0 = tanhf(uf.x), th1 = tanhf(uf.y);
        float2 hn;
        hn.x = hown.x + DT_TAU * (z0 - 1.f) * (hown.x - th0);
        hn.y = hown.y + DT_TAU * (z1 - 1.f) * (hown.y - th1);
        *(float2*)&g_h[(size_t)(b0 + bb) * NR + j0 + jj0] = hn;
        *(float2*)&out_h[((size_t)(b0 + bb) * TT + t) * NR + j0 + jj0] = hn;

        group_barrier(gm, bidx);  // h(t+1) visible group-wide
        if (t + 1 < TT)
            issue_stage(g_h, smu + HS_OFF, x, smu + XT_OFF, b0, t + 1, true, tid);
    }
}

// ---------------- decoder: y = h @ W_dec^T  (f32x2 tiled GEMM) ----------------
__global__ void __launch_bounds__(256)
decoder_kernel(const float* __restrict__ h, const float* __restrict__ W,
               float* __restrict__ y) {
    __shared__ float HT[32 * 132];
    __shared__ float WT[32 * 68];
    const int tid = threadIdx.x;
    const int bt0 = blockIdx.x * 128;
    const int o0  = blockIdx.y * 64;
    const int rg = tid & 15;
    const int cg = tid >> 4;
    const int col0 = cg * 4;
    const int lrow = tid >> 1, lkh = (tid & 1) * 16;
    const int lcol = tid >> 2, lkw = (tid & 3) * 8;

    u64 acc[4][4];
#pragma unroll
    for (int i = 0; i < 4; i++)
#pragma unroll
        for (int c = 0; c < 4; c++) acc[i][c] = 0ull;

    for (int k0 = 0; k0 < NR; k0 += 32) {
        __syncthreads();
        const float4* hsrc =
            (const float4*)(h + (size_t)(bt0 + lrow) * NR + k0 + lkh);
#pragma unroll
        for (int j = 0; j < 4; j++) {
            float4 v = hsrc[j];
            int kk = lkh + 4 * j;
            HT[(kk + 0) * 132 + lrow] = v.x;
            HT[(kk + 1) * 132 + lrow] = v.y;
            HT[(kk + 2) * 132 + lrow] = v.z;
            HT[(kk + 3) * 132 + lrow] = v.w;
        }
        const float4* wsrc =
            (const float4*)(W + (size_t)(o0 + lcol) * NR + k0 + lkw);
#pragma unroll
        for (int j = 0; j < 2; j++) {
            float4 v = wsrc[j];
            int kk = lkw + 4 * j;
            WT[(kk + 0) * 68 + lcol] = v.x;
            WT[(kk + 1) * 68 + lcol] = v.y;
            WT[(kk + 2) * 68 + lcol] = v.z;
            WT[(kk + 3) * 68 + lcol] = v.w;
        }
        __syncthreads();
#pragma unroll 4
        for (int k = 0; k < 32; k++) {
            const u64* HTd = (const u64*)(HT + k * 132);
            u64 h0 = HTd[rg];
            u64 h1 = HTd[rg + 16];
            u64 h2 = HTd[rg + 32];
            u64 h3 = HTd[rg + 48];
            float4 wv = *(const float4*)(WT + k * 68 + col0);
            u64 w0 = pack2(wv.x, wv.x);
            u64 w1 = pack2(wv.y, wv.y);
            u64 w2 = pack2(wv.z, wv.z);
            u64 w3 = pack2(wv.w, wv.w);
            acc[0][0] = ffma2(h0, w0, acc[0][0]);
            acc[0][1] = ffma2(h0, w1, acc[0][1]);
            acc[0][2] = ffma2(h0, w2, acc[0][2]);
            acc[0][3] = ffma2(h0, w3, acc[0][3]);
            acc[1][0] = ffma2(h1, w0, acc[1][0]);
            acc[1][1] = ffma2(h1, w1, acc[1][1]);
            acc[1][2] = ffma2(h1, w2, acc[1][2]);
            acc[1][3] = ffma2(h1, w3, acc[1][3]);
            acc[2][0] = ffma2(h2, w0, acc[2][0]);
            acc[2][1] = ffma2(h2, w1, acc[2][1]);
            acc[2][2] = ffma2(h2, w2, acc[2][2]);
            acc[2][3] = ffma2(h2, w3, acc[2][3]);
            acc[3][0] = ffma2(h3, w0, acc[3][0]);
            acc[3][1] = ffma2(h3, w1, acc[3][1]);
            acc[3][2] = ffma2(h3, w2, acc[3][2]);
            acc[3][3] = ffma2(h3, w3, acc[3][3]);
        }
    }
#pragma unroll
    for (int i = 0; i < 4; i++) {
        int r = 2 * rg + 32 * i;
        float2 p0 = unpack2(acc[i][0]);
        float2 p1 = unpack2(acc[i][1]);
        float2 p2 = unpack2(acc[i][2]);
        float2 p3 = unpack2(acc[i][3]);
        float4 ra = make_float4(p0.x, p1.x, p2.x, p3.x);
        float4 rb = make_float4(p0.y, p1.y, p2.y, p3.y);
        *(float4*)(y + (size_t)(bt0 + r) * NOUT + o0 + col0) = ra;
        *(float4*)(y + (size_t)(bt0 + r + 1) * NOUT + o0 + col0) = rb;
    }
}

// ---------------- launch -------------------------------------------------------
// Order: rnn -> decoder -> reset. (reset last keeps barrier state zeroed for
// the next graph replay; static init covers the very first run.)
extern "C" void kernel_launch(void* const* d_in, const int* in_sizes, int n_in,
                              void* d_out, int out_size) {
    const float* x          = (const float*)d_in[0];
    const float* init_state = (const float*)d_in[1];
    const float* W_enc      = (const float*)d_in[2];
    const float* W_wz       = (const float*)d_in[3];
    const float* W_uz       = (const float*)d_in[4];
    const float* W_wr       = (const float*)d_in[5];
    const float* W_ur       = (const float*)d_in[6];
    const float* W_wh       = (const float*)d_in[7];
    const float* W_uh       = (const float*)d_in[8];
    const float* W_dec      = (const float*)d_in[9];
    float* out = (float*)d_out;

    cudaFuncSetAttribute(rnn_persistent,
                         cudaFuncAttributeMaxDynamicSharedMemorySize, SMEM_TOTAL);

    rnn_persistent<<<PM * PN, NTH, SMEM_TOTAL>>>(
        x, init_state, W_enc, W_wz, W_uz, W_wr, W_ur, W_wh, W_uh, out);

    size_t hN = (size_t)BN * TT * NR;
    if ((size_t)out_size >= 2 * hN) {
        dim3 grid((BN * TT) / 128, NOUT / 64);
        decoder_kernel<<<grid, 256>>>(out, W_dec, out + hN);
    }

    reset_bar_kernel<<<1, 32>>>();
}

// round 11
// speedup vs baseline: 1.2610x; 1.0304x over previous
#include <cuda_runtime.h>
#include <cstdint>

// Problem dims
#define BN    128
#define TT    512
#define NR    512
#define NOUT  512
#define PM    4     // batch groups
#define PN    32    // neuron-slice CTAs per group
#define MB    32    // batch rows per group
#define NJ    16    // neurons per CTA
#define NTH   512
#define DT_TAU 0.2f

typedef unsigned long long u64;

// ---------------- global scratch ---------------------------------------------
__device__ float g_h[BN * NR];
__device__ float g_rh[BN * NR];
__device__ unsigned g_cnt[PM];
__device__ volatile unsigned g_gen[PM];

// ---------------- f32x2 helpers ----------------------------------------------
__device__ __forceinline__ u64 ffma2(u64 a, u64 b, u64 c) {
    u64 d;
    asm("fma.rn.f32x2 %0, %1, %2, %3;" : "=l"(d) : "l"(a), "l"(b), "l"(c));
    return d;
}
__device__ __forceinline__ u64 addf2(u64 a, u64 b) {
    u64 d;
    asm("add.rn.f32x2 %0, %1, %2;" : "=l"(d) : "l"(a), "l"(b));
    return d;
}
__device__ __forceinline__ u64 pack2(float lo, float hi) {
    u64 d;
    asm("mov.b64 %0, {%1, %2};" : "=l"(d) : "f"(lo), "f"(hi));
    return d;
}
__device__ __forceinline__ float2 unpack2(u64 d) {
    float2 r;
    asm("mov.b64 {%0, %1}, %2;" : "=f"(r.x), "=f"(r.y) : "l"(d));
    return r;
}
__device__ __forceinline__ void cp16(unsigned dst, const void* src) {
    asm volatile("cp.async.cg.shared.global [%0], [%1], 16;"
                 :: "r"(dst), "l"(src) : "memory");
}
__device__ __forceinline__ void cp8(unsigned dst, const void* src) {
    asm volatile("cp.async.ca.shared.global [%0], [%1], 8;"
                 :: "r"(dst), "l"(src) : "memory");
}
#define CP_COMMIT() asm volatile("cp.async.commit_group;" ::: "memory")
#define CP_WAIT0()  asm volatile("cp.async.wait_group 0;" ::: "memory")

// ---------------- SMEM layout (byte offsets) ----------------------------------
#define WZR_OFF   0
#define WH2_OFF   65536
#define WH2_ROWD  514
#define HS_OFF    (WH2_OFF + 8 * WH2_ROWD * 8)            // 98432
#define HS_STRIDE 2064
#define XT_OFF    (HS_OFF + MB * HS_STRIDE)               // 164480
#define WZRX_OFF  (XT_OFF + 256)                          // 164736
#define WHX_OFF   (WZRX_OFF + 256)                        // 164992
#define PART_OFF  (WHX_OFF + 128)                         // 165120
#define SMEM_TOTAL (PART_OFF + 2048)                      // 167168

// ---------------- group barrier (R5 atomic version, launch-reset) -------------
__device__ __forceinline__ void group_barrier(int g, unsigned& idx) {
    __syncthreads();
    if (threadIdx.x == 0) {
        __threadfence();  // release: publish this CTA's global stores
        unsigned old = atomicAdd(&g_cnt[g], 1u);
        if (old == idx * (unsigned)PN + (PN - 1)) {
            __threadfence();
            g_gen[g] = idx + 1u;
        } else {
            while (g_gen[g] < idx + 1u) {}
            __threadfence();  // acquire
        }
    }
    __syncthreads();
    idx++;
}

// Runs LAST each replay: leaves barrier state zeroed for the next replay.
__global__ void reset_bar_kernel() {
    int i = threadIdx.x;
    if (i < PM) { g_cnt[i] = 0u; g_gen[i] = 0u; }
}

// ---------------- async staging: 32 rows x 512 floats -> HS -------------------
// 512 threads: 16 threads per row, 8 x 16B each.
__device__ __forceinline__ void issue_stage(const float* __restrict__ src,
                                            unsigned hs_u32,
                                            const float* __restrict__ xsrc,
                                            unsigned xt_u32, int b0, int t,
                                            bool do_x, int tid) {
    int row = tid >> 4, c0 = tid & 15;
    const float4* s = (const float4*)(src + (size_t)(b0 + row) * NR) + c0;
    unsigned d = hs_u32 + row * HS_STRIDE + c0 * 16;
#pragma unroll
    for (int i = 0; i < 8; i++) cp16(d + i * 256, s + 16 * i);
    if (do_x && tid < 32)
        cp8(xt_u32 + tid * 8, xsrc + ((size_t)(b0 + tid) * TT + t) * 2);
    CP_COMMIT();
}

// full dot over K=512 (prologue h0 only; kh0 threads)
__device__ __forceinline__ u64 dot512(const float4* __restrict__ hr4,
                                      const ulonglong2* __restrict__ w,
                                      u64 init) {
    u64 u = init, ub = 0ull;
#pragma unroll 8
    for (int k4 = 0; k4 < 128; k4++) {
        float4 v = hr4[k4];
        ulonglong2 wa = w[2 * k4];
        ulonglong2 wb = w[2 * k4 + 1];
        u  = ffma2(pack2(v.x, v.x), wa.x, u);
        ub = ffma2(pack2(v.y, v.y), wa.y, ub);
        u  = ffma2(pack2(v.z, v.z), wb.x, u);
        ub = ffma2(pack2(v.w, v.w), wb.y, ub);
    }
    return addf2(u, ub);
}

// ---------------- persistent recurrent kernel ---------------------------------
__global__ void __launch_bounds__(NTH, 1)
rnn_persistent(const float* __restrict__ x, const float* __restrict__ init_state,
               const float* __restrict__ W_enc, const float* __restrict__ W_wz,
               const float* __restrict__ W_uz, const float* __restrict__ W_wr,
               const float* __restrict__ W_ur, const float* __restrict__ W_wh,
               const float* __restrict__ W_uh, float* __restrict__ out_h) {
    extern __shared__ char smem[];
    const int tid = threadIdx.x;
    const int gm = blockIdx.x & 3;
    const int gn = blockIdx.x >> 2;
    const int b0 = gm * MB;
    const int j0 = gn * NJ;
    // warp = 4 jp-quartet x 8 bb; jph and kh are warp-uniform bits.
    const int jp = (tid & 3) + 4 * ((tid >> 7) & 1);
    const int bb = (tid >> 2) & 31;
    const int kh = tid >> 8;              // k-half: warp-uniform
    const int jj0 = 2 * jp;
    const int pidx = tid & 255;           // partner index in PART
    const unsigned smu = (unsigned)__cvta_generic_to_shared(smem);
    unsigned bidx = 0;

    float* WZRf = (float*)(smem + WZR_OFF);
    float* WH2f = (float*)(smem + WH2_OFF);
    const ulonglong2* WZRd2 = (const ulonglong2*)(smem + WZR_OFF);
    const ulonglong2* WHrow =
        (const ulonglong2*)(smem + WH2_OFF) + jp * (WH2_ROWD / 2);
    u64* wzrx = (u64*)(smem + WZRX_OFF);
    u64* whx  = (u64*)(smem + WHX_OFF);
    float2* xts = (float2*)(smem + XT_OFF);
    u64* PART = (u64*)(smem + PART_OFF);
    const float4* hrow4 = (const float4*)(smem + HS_OFF + bb * HS_STRIDE);

    // ---- prologue: stage init_state; W_enc slice into WH2 layout ----
    issue_stage(init_state, smu + HS_OFF, x, smu + XT_OFF, b0, 0, false, tid);
    for (int idx = tid; idx < 8 * NR; idx += NTH) {
        int p = idx >> 9, k = idx & 511;
        WH2f[p * 2 * WH2_ROWD + 2 * k]     = W_enc[(size_t)(j0 + 2 * p) * NR + k];
        WH2f[p * 2 * WH2_ROWD + 2 * k + 1] = W_enc[(size_t)(j0 + 2 * p + 1) * NR + k];
    }
    CP_WAIT0();
    __syncthreads();
    if (kh == 0) {  // full-K encoder dot by the low half (one-time)
        u64 h0d = dot512(hrow4, WHrow, 0ull);
        *(float2*)&g_h[(size_t)(b0 + bb) * NR + j0 + jj0] = unpack2(h0d);
    }
    __syncthreads();  // all reads of WH2/HS done before overwrite

    // ---- stationary recurrent weights ----
    for (int idx = tid; idx < NJ * NR; idx += NTH) {
        int jj = idx >> 9, k = idx & 511;
        WZRf[k * 32 + 2 * jj]     = W_uz[(size_t)(j0 + jj) * NR + k];
        WZRf[k * 32 + 2 * jj + 1] = W_ur[(size_t)(j0 + jj) * NR + k];
    }
    for (int idx = tid; idx < 8 * NR; idx += NTH) {
        int p = idx >> 9, k = idx & 511;
        WH2f[p * 2 * WH2_ROWD + 2 * k]     = W_uh[(size_t)(j0 + 2 * p) * NR + k];
        WH2f[p * 2 * WH2_ROWD + 2 * k + 1] = W_uh[(size_t)(j0 + 2 * p + 1) * NR + k];
    }
    if (tid < NJ) {
        wzrx[tid]      = pack2(W_wz[(j0 + tid) * 2 + 0], W_wr[(j0 + tid) * 2 + 0]);
        wzrx[16 + tid] = pack2(W_wz[(j0 + tid) * 2 + 1], W_wr[(j0 + tid) * 2 + 1]);
    }
    if (tid < 8) {
        whx[tid]     = pack2(W_wh[(j0 + 2 * tid) * 2 + 0], W_wh[(j0 + 2 * tid + 1) * 2 + 0]);
        whx[8 + tid] = pack2(W_wh[(j0 + 2 * tid) * 2 + 1], W_wh[(j0 + 2 * tid + 1) * 2 + 1]);
    }
    group_barrier(gm, bidx);  // h0 visible group-wide
    issue_stage(g_h, smu + HS_OFF, x, smu + XT_OFF, b0, 0, true, tid);

    u64 x0p = 0ull, x1p = 0ull;
    float z0 = 0.f, z1 = 0.f;
    float2 hown = make_float2(0.f, 0.f);

    for (int t = 0; t < TT; t++) {
        // ---------------- phase 1: z, r, r*h (k-split halves) ----------------
        CP_WAIT0();
        __syncthreads();
        u64 a0, a1, a0b = 0ull, a1b = 0ull;
        if (kh == 0) {
            float2 xt = xts[bb];
            x0p = pack2(xt.x, xt.x);
            x1p = pack2(xt.y, xt.y);
            a0 = ffma2(x0p, wzrx[jj0],     ffma2(x1p, wzrx[16 + jj0],     0ull));
            a1 = ffma2(x0p, wzrx[jj0 + 1], ffma2(x1p, wzrx[16 + jj0 + 1], 0ull));
        } else { a0 = 0ull; a1 = 0ull; }
        {
            const ulonglong2* wz = WZRd2 + jp;
            const float4* hr = hrow4 + kh * 64;
            const int kb = kh * 64;
#pragma unroll 8
            for (int i = 0; i < 64; i++) {
                int k4 = kb + i;
                float4 hv = hr[i];
                u64 hx = pack2(hv.x, hv.x);
                ulonglong2 w0 = wz[(4 * k4 + 0) * 8];
                a0  = ffma2(hx, w0.x, a0);  a1  = ffma2(hx, w0.y, a1);
                u64 hy = pack2(hv.y, hv.y);
                ulonglong2 w1 = wz[(4 * k4 + 1) * 8];
                a0b = ffma2(hy, w1.x, a0b); a1b = ffma2(hy, w1.y, a1b);
                u64 hz = pack2(hv.z, hv.z);
                ulonglong2 w2 = wz[(4 * k4 + 2) * 8];
                a0  = ffma2(hz, w2.x, a0);  a1  = ffma2(hz, w2.y, a1);
                u64 hw = pack2(hv.w, hv.w);
                ulonglong2 w3 = wz[(4 * k4 + 3) * 8];
                a0b = ffma2(hw, w3.x, a0b); a1b = ffma2(hw, w3.y, a1b);
            }
        }
        a0 = addf2(a0, a0b);
        a1 = addf2(a1, a1b);
        // 2-round reduction through PART (2048 B)
        if (kh) PART[pidx] = a0;
        __syncthreads();
        if (!kh) a0 = addf2(a0, PART[pidx]);
        __syncthreads();
        if (kh) PART[pidx] = a1;
        __syncthreads();
        if (!kh) {
            a1 = addf2(a1, PART[pidx]);
            float2 zr0 = unpack2(a0), zr1 = unpack2(a1);
            z0 = 1.f / (1.f + __expf(-zr0.x));
            float r0 = 1.f / (1.f + __expf(-zr0.y));
            z1 = 1.f / (1.f + __expf(-zr1.x));
            float r1 = 1.f / (1.f + __expf(-zr1.y));
            hown = *(const float2*)(smem + HS_OFF + bb * HS_STRIDE +
                                    (size_t)(j0 + jj0) * 4);
            float2 rh = make_float2(r0 * hown.x, r1 * hown.y);
            *(float2*)&g_rh[(size_t)(b0 + bb) * NR + j0 + jj0] = rh;
        }

        group_barrier(gm, bidx);  // rh visible group-wide
        issue_stage(g_rh, smu + HS_OFF, x, smu + XT_OFF, b0, 0, false, tid);

        // ---------------- phase 2: u, tanh, h update ----------------
        CP_WAIT0();
        __syncthreads();
        u64 uu, ub = 0ull;
        uu = (kh == 0) ? ffma2(x0p, whx[jp], ffma2(x1p, whx[8 + jp], 0ull))
                       : 0ull;
        {
            const ulonglong2* w = WHrow + kh * 128;
            const float4* hr = hrow4 + kh * 64;
#pragma unroll 8
            for (int i = 0; i < 64; i++) {
                float4 v = hr[i];
                ulonglong2 wa = w[2 * i];
                ulonglong2 wb = w[2 * i + 1];
                uu = ffma2(pack2(v.x, v.x), wa.x, uu);
                ub = ffma2(pack2(v.y, v.y), wa.y, ub);
                uu = ffma2(pack2(v.z, v.z), wb.x, uu);
                ub = ffma2(pack2(v.w, v.w), wb.y, ub);
            }
        }
        uu = addf2(uu, ub);
        if (kh) PART[pidx] = uu;
        __syncthreads();
        if (!kh) {
            uu = addf2(uu, PART[pidx]);
            float2 uf = unpack2(uu);
            float th0 = tanhf(uf.x), th1 = tanhf(uf.y);
            float2 hn;
            hn.x = hown.x + DT_TAU * (z0 - 1.f) * (hown.x - th0);
            hn.y = hown.y + DT_TAU * (z1 - 1.f) * (hown.y - th1);
            *(float2*)&g_h[(size_t)(b0 + bb) * NR + j0 + jj0] = hn;
            *(float2*)&out_h[((size_t)(b0 + bb) * TT + t) * NR + j0 + jj0] = hn;
        }

        group_barrier(gm, bidx);  // h(t+1) visible group-wide
        if (t + 1 < TT)
            issue_stage(g_h, smu + HS_OFF, x, smu + XT_OFF, b0, t + 1, true, tid);
    }
}

// ---------------- decoder: y = h @ W_dec^T  (f32x2 tiled GEMM) ----------------
__global__ void __launch_bounds__(256)
decoder_kernel(const float* __restrict__ h, const float* __restrict__ W,
               float* __restrict__ y) {
    __shared__ float HT[32 * 132];
    __shared__ float WT[32 * 68];
    const int tid = threadIdx.x;
    const int bt0 = blockIdx.x * 128;
    const int o0  = blockIdx.y * 64;
    const int rg = tid & 15;
    const int cg = tid >> 4;
    const int col0 = cg * 4;
    const int lrow = tid >> 1, lkh = (tid & 1) * 16;
    const int lcol = tid >> 2, lkw = (tid & 3) * 8;

    u64 acc[4][4];
#pragma unroll
    for (int i = 0; i < 4; i++)
#pragma unroll
        for (int c = 0; c < 4; c++) acc[i][c] = 0ull;

    for (int k0 = 0; k0 < NR; k0 += 32) {
        __syncthreads();
        const float4* hsrc =
            (const float4*)(h + (size_t)(bt0 + lrow) * NR + k0 + lkh);
#pragma unroll
        for (int j = 0; j < 4; j++) {
            float4 v = hsrc[j];
            int kk = lkh + 4 * j;
            HT[(kk + 0) * 132 + lrow] = v.x;
            HT[(kk + 1) * 132 + lrow] = v.y;
            HT[(kk + 2) * 132 + lrow] = v.z;
            HT[(kk + 3) * 132 + lrow] = v.w;
        }
        const float4* wsrc =
            (const float4*)(W + (size_t)(o0 + lcol) * NR + k0 + lkw);
#pragma unroll
        for (int j = 0; j < 2; j++) {
            float4 v = wsrc[j];
            int kk = lkw + 4 * j;
            WT[(kk + 0) * 68 + lcol] = v.x;
            WT[(kk + 1) * 68 + lcol] = v.y;
            WT[(kk + 2) * 68 + lcol] = v.z;
            WT[(kk + 3) * 68 + lcol] = v.w;
        }
        __syncthreads();
#pragma unroll 4
        for (int k = 0; k < 32; k++) {
            const u64* HTd = (const u64*)(HT + k * 132);
            u64 h0 = HTd[rg];
            u64 h1 = HTd[rg + 16];
            u64 h2 = HTd[rg + 32];
            u64 h3 = HTd[rg + 48];
            float4 wv = *(const float4*)(WT + k * 68 + col0);
            u64 w0 = pack2(wv.x, wv.x);
            u64 w1 = pack2(wv.y, wv.y);
            u64 w2 = pack2(wv.z, wv.z);
            u64 w3 = pack2(wv.w, wv.w);
            acc[0][0] = ffma2(h0, w0, acc[0][0]);
            acc[0][1] = ffma2(h0, w1, acc[0][1]);
            acc[0][2] = ffma2(h0, w2, acc[0][2]);
            acc[0][3] = ffma2(h0, w3, acc[0][3]);
            acc[1][0] = ffma2(h1, w0, acc[1][0]);
            acc[1][1] = ffma2(h1, w1, acc[1][1]);
            acc[1][2] = ffma2(h1, w2, acc[1][2]);
            acc[1][3] = ffma2(h1, w3, acc[1][3]);
            acc[2][0] = ffma2(h2, w0, acc[2][0]);
            acc[2][1] = ffma2(h2, w1, acc[2][1]);
            acc[2][2] = ffma2(h2, w2, acc[2][2]);
            acc[2][3] = ffma2(h2, w3, acc[2][3]);
            acc[3][0] = ffma2(h3, w0, acc[3][0]);
            acc[3][1] = ffma2(h3, w1, acc[3][1]);
            acc[3][2] = ffma2(h3, w2, acc[3][2]);
            acc[3][3] = ffma2(h3, w3, acc[3][3]);
        }
    }
#pragma unroll
    for (int i = 0; i < 4; i++) {
        int r = 2 * rg + 32 * i;
        float2 p0 = unpack2(acc[i][0]);
        float2 p1 = unpack2(acc[i][1]);
        float2 p2 = unpack2(acc[i][2]);
        float2 p3 = unpack2(acc[i][3]);
        float4 ra = make_float4(p0.x, p1.x, p2.x, p3.x);
        float4 rb = make_float4(p0.y, p1.y, p2.y, p3.y);
        *(float4*)(y + (size_t)(bt0 + r) * NOUT + o0 + col0) = ra;
        *(float4*)(y + (size_t)(bt0 + r + 1) * NOUT + o0 + col0) = rb;
    }
}

// ---------------- launch -------------------------------------------------------
extern "C" void kernel_launch(void* const* d_in, const int* in_sizes, int n_in,
                              void* d_out, int out_size) {
    const float* x          = (const float*)d_in[0];
    const float* init_state = (const float*)d_in[1];
    const float* W_enc      = (const float*)d_in[2];
    const float* W_wz       = (const float*)d_in[3];
    const float* W_uz       = (const float*)d_in[4];
    const float* W_wr       = (const float*)d_in[5];
    const float* W_ur       = (const float*)d_in[6];
    const float* W_wh       = (const float*)d_in[7];
    const float* W_uh       = (const float*)d_in[8];
    const float* W_dec      = (const float*)d_in[9];
    float* out = (float*)d_out;

    cudaFuncSetAttribute(rnn_persistent,
                         cudaFuncAttributeMaxDynamicSharedMemorySize, SMEM_TOTAL);

    rnn_persistent<<<PM * PN, NTH, SMEM_TOTAL>>>(
        x, init_state, W_enc, W_wz, W_uz, W_wr, W_ur, W_wh, W_uh, out);

    size_t hN = (size_t)BN * TT * NR;
    if ((size_t)out_size >= 2 * hN) {
        dim3 grid((BN * TT) / 128, NOUT / 64);
        decoder_kernel<<<grid, 256>>>(out, W_dec, out + hN);
    }

    reset_bar_kernel<<<1, 32>>>();
}

// round 13
// speedup vs baseline: 1.7215x; 1.3652x over previous
#include <cuda_runtime.h>
#include <cstdint>

#define BN 128
#define TT 512
#define NR 512
#define NOUT 512
#define PM 4
#define PN 32
#define MB 32
#define NJ 16
#define NTH 256
#define DT_TAU 0.2f

typedef unsigned long long u64;

// ---------------- global scratch ---------------------------------------------
__device__ float g_h[BN * NR];
__device__ float g_rh[BN * NR];
__device__ unsigned g_cnt[PM];
__device__ volatile unsigned g_gen[PM];

// ---------------- f32x2 helpers ----------------------------------------------
__device__ __forceinline__ u64 ffma2(u64 a, u64 b, u64 c) {
    u64 d;
    asm("fma.rn.f32x2 %0, %1, %2, %3;" : "=l"(d) : "l"(a), "l"(b), "l"(c));
    return d;
}
__device__ __forceinline__ u64 addf2(u64 a, u64 b) {
    u64 d;
    asm("add.rn.f32x2 %0, %1, %2;" : "=l"(d) : "l"(a), "l"(b));
    return d;
}
__device__ __forceinline__ u64 pack2(float lo, float hi) {
    u64 d;
    asm("mov.b64 %0, {%1, %2};" : "=l"(d) : "f"(lo), "f"(hi));
    return d;
}
__device__ __forceinline__ float2 unpack2(u64 d) {
    float2 r;
    asm("mov.b64 {%0, %1}, %2;" : "=f"(r.x), "=f"(r.y) : "l"(d));
    return r;
}
__device__ __forceinline__ void cp16(unsigned dst, const void* src) {
    asm volatile("cp.async.cg.shared.global [%0], [%1], 16;"
                 :: "r"(dst), "l"(src) : "memory");
}
__device__ __forceinline__ void cp8(unsigned dst, const void* src) {
    asm volatile("cp.async.ca.shared.global [%0], [%1], 8;"
                 :: "r"(dst), "l"(src) : "memory");
}
#define CP_COMMIT() asm volatile("cp.async.commit_group;" ::: "memory")
#define CP_WAIT0()  asm volatile("cp.async.wait_group 0;" ::: "memory")

// ---------------- SMEM layout -------------------------------------------------
// WZR : [kpair p][neuron jj] ull2 {z(k0,k1), r(k0,k1)} : 256*16*16 = 65536
// WH  : [kpair p][npair q]   ull2 {w2q(k0k1), w2q+1(k0k1)} : 256*8*16 = 32768
// HS  : 32 rows x (512 f + 16B pad)                      : 66048
// XT  : 32 float2; XW: 6 x 16 floats; ZBUF: 32x16 u64; PART: 4x64x8 u64
#define WZR_OFF   0
#define WH_OFF    65536
#define HS_OFF    98304
#define HS_STRIDE 2064
#define XT_OFF    164352
#define XW_OFF    164608
#define ZBUF_OFF  164992
#define PART_OFF  169088
#define SMEM_TOTAL 185472

// ---------------- group barrier (proven R5/R10 version) -----------------------
__device__ __forceinline__ void group_barrier(int g, unsigned& idx) {
    __syncthreads();
    if (threadIdx.x == 0) {
        __threadfence();
        unsigned old = atomicAdd(&g_cnt[g], 1u);
        if (old == idx * (unsigned)PN + (PN - 1)) {
            __threadfence();
            g_gen[g] = idx + 1u;
        } else {
            while (g_gen[g] < idx + 1u) {}
            __threadfence();
        }
    }
    __syncthreads();
    idx++;
}

__global__ void reset_bar_kernel() {
    int i = threadIdx.x;
    if (i < PM) { g_cnt[i] = 0u; g_gen[i] = 0u; }
}

// ---------------- async staging: 32 rows x 512 floats -> HS -------------------
__device__ __forceinline__ void issue_stage(const float* __restrict__ src,
                                            unsigned hs_u32,
                                            const float* __restrict__ xsrc,
                                            unsigned xt_u32, int b0, int t,
                                            bool do_x, int tid) {
    int row = tid >> 3, c0 = tid & 7;
    const float4* s = (const float4*)(src + (size_t)(b0 + row) * NR) + c0;
    unsigned d = hs_u32 + row * HS_STRIDE + c0 * 16;
#pragma unroll
    for (int i = 0; i < 16; i++) cp16(d + i * 128, s + 8 * i);
    if (do_x && tid < 32)
        cp8(xt_u32 + tid * 8, xsrc + ((size_t)(b0 + tid) * TT + t) * 2);
    CP_COMMIT();
}

// ---------------- phase2-style dot: acc[r][n] (k-even/odd packed) -------------
__device__ __forceinline__ void dot_wh4(const char* hbase,
                                        const ulonglong2* __restrict__ WHu2,
                                        int jp, int kq, u64 acc[4][2]) {
#pragma unroll
    for (int r = 0; r < 4; r++) { acc[r][0] = 0ull; acc[r][1] = 0ull; }
#pragma unroll 8
    for (int k4 = 32 * kq; k4 < 32 * kq + 32; k4++) {
        ulonglong2 h0v = *(const ulonglong2*)(hbase + 0 * HS_STRIDE + k4 * 16);
        ulonglong2 h1v = *(const ulonglong2*)(hbase + 1 * HS_STRIDE + k4 * 16);
        ulonglong2 h2v = *(const ulonglong2*)(hbase + 2 * HS_STRIDE + k4 * 16);
        ulonglong2 h3v = *(const ulonglong2*)(hbase + 3 * HS_STRIDE + k4 * 16);
        ulonglong2 wA = WHu2[(2 * k4) * 8 + jp];
        ulonglong2 wB = WHu2[(2 * k4 + 1) * 8 + jp];
        acc[0][0] = ffma2(h0v.x, wA.x, acc[0][0]);
        acc[0][1] = ffma2(h0v.x, wA.y, acc[0][1]);
        acc[1][0] = ffma2(h1v.x, wA.x, acc[1][0]);
        acc[1][1] = ffma2(h1v.x, wA.y, acc[1][1]);
        acc[2][0] = ffma2(h2v.x, wA.x, acc[2][0]);
        acc[2][1] = ffma2(h2v.x, wA.y, acc[2][1]);
        acc[3][0] = ffma2(h3v.x, wA.x, acc[3][0]);
        acc[3][1] = ffma2(h3v.x, wA.y, acc[3][1]);
        acc[0][0] = ffma2(h0v.y, wB.x, acc[0][0]);
        acc[0][1] = ffma2(h0v.y, wB.y, acc[0][1]);
        acc[1][0] = ffma2(h1v.y, wB.x, acc[1][0]);
        acc[1][1] = ffma2(h1v.y, wB.y, acc[1][1]);
        acc[2][0] = ffma2(h2v.y, wB.x, acc[2][0]);
        acc[2][1] = ffma2(h2v.y, wB.y, acc[2][1]);
        acc[3][0] = ffma2(h3v.y, wB.x, acc[3][0]);
        acc[3][1] = ffma2(h3v.y, wB.y, acc[3][1]);
    }
}

// ---------------- persistent recurrent kernel ---------------------------------
__global__ void __launch_bounds__(NTH, 1)
rnn_persistent(const float* __restrict__ x, const float* __restrict__ init_state,
               const float* __restrict__ W_enc, const float* __restrict__ W_wz,
               const float* __restrict__ W_uz, const float* __restrict__ W_wr,
               const float* __restrict__ W_ur, const float* __restrict__ W_wh,
               const float* __restrict__ W_uh, float* __restrict__ out_h) {
    extern __shared__ char smem[];
    const int tid = threadIdx.x;
    const int gm = blockIdx.x & 3;
    const int gn = blockIdx.x >> 2;
    const int b0 = gm * MB;
    const int j0 = gn * NJ;
    const int kq = tid >> 6;        // k-quarter (warp-uniform)
    const int u  = tid & 63;        // work unit
    const int jp = u & 7;           // neuron pair (n0=2jp, n1=2jp+1)
    const int rg = u >> 3;          // row group (rows 4rg..4rg+3)
    const int n0 = 2 * jp, n1 = n0 + 1;
    const unsigned smu = (unsigned)__cvta_generic_to_shared(smem);
    unsigned bidx = 0;

    ulonglong2* WZRu2 = (ulonglong2*)(smem + WZR_OFF);
    ulonglong2* WHu2  = (ulonglong2*)(smem + WH_OFF);
    float* wxz0 = (float*)(smem + XW_OFF);
    float* wxz1 = wxz0 + 16;
    float* wxr0 = wxz0 + 32;
    float* wxr1 = wxz0 + 48;
    float* wxh0 = wxz0 + 64;
    float* wxh1 = wxz0 + 80;
    u64*   ZBUF = (u64*)(smem + ZBUF_OFF);
    u64*   PART = (u64*)(smem + PART_OFF);
    float* PARTF = (float*)(smem + PART_OFF);
    float2* xts = (float2*)(smem + XT_OFF);
    const char* hbase = smem + HS_OFF + (4 * rg) * HS_STRIDE;

    // ---- prologue: stage init_state; W_enc into WH layout ----
    issue_stage(init_state, smu + HS_OFF, x, smu + XT_OFF, b0, 0, false, tid);
    for (int idx = tid; idx < 2048; idx += NTH) {
        int p = idx & 255, q = idx >> 8;
        float2 a = *(const float2*)&W_enc[(size_t)(j0 + 2 * q) * NR + 2 * p];
        float2 b = *(const float2*)&W_enc[(size_t)(j0 + 2 * q + 1) * NR + 2 * p];
        WHu2[p * 8 + q] = make_ulonglong2(pack2(a.x, a.y), pack2(b.x, b.y));
    }
    CP_WAIT0();
    __syncthreads();
    {   // h0 = init_state @ W_enc^T
        u64 acc[4][2];
        dot_wh4(hbase, WHu2, jp, kq, acc);
#pragma unroll
        for (int r = 0; r < 4; r++)
#pragma unroll
            for (int n = 0; n < 2; n++) {
                float2 t2 = unpack2(acc[r][n]);
                PARTF[(kq * 64 + u) * 8 + r * 2 + n] = t2.x + t2.y;
            }
    }
    __syncthreads();
#pragma unroll
    for (int it = 0; it < 2; it++) {
        int j = 2 * tid + it;
        int row = j >> 4, c = j & 15;
        int uu = (row >> 2) * 8 + (c >> 1);
        int ii = (row & 3) * 2 + (c & 1);
        float s = PARTF[uu * 8 + ii] + PARTF[(64 + uu) * 8 + ii] +
                  PARTF[(128 + uu) * 8 + ii] + PARTF[(192 + uu) * 8 + ii];
        g_h[(size_t)(b0 + row) * NR + j0 + c] = s;
    }
    __syncthreads();

    // ---- stationary weights: WZR (z,r kpair-packed), WH = W_uh, x tables ----
    for (int idx = tid; idx < 4096; idx += NTH) {
        int p = idx & 255, jj = idx >> 8;
        float2 wz = *(const float2*)&W_uz[(size_t)(j0 + jj) * NR + 2 * p];
        float2 wr = *(const float2*)&W_ur[(size_t)(j0 + jj) * NR + 2 * p];
        WZRu2[p * 16 + jj] = make_ulonglong2(pack2(wz.x, wz.y), pack2(wr.x, wr.y));
    }
    for (int idx = tid; idx < 2048; idx += NTH) {
        int p = idx & 255, q = idx >> 8;
        float2 a = *(const float2*)&W_uh[(size_t)(j0 + 2 * q) * NR + 2 * p];
        float2 b = *(const float2*)&W_uh[(size_t)(j0 + 2 * q + 1) * NR + 2 * p];
        WHu2[p * 8 + q] = make_ulonglong2(pack2(a.x, a.y), pack2(b.x, b.y));
    }
    if (tid < 16) {
        wxz0[tid] = W_wz[(j0 + tid) * 2 + 0];
        wxz1[tid] = W_wz[(j0 + tid) * 2 + 1];
        wxr0[tid] = W_wr[(j0 + tid) * 2 + 0];
        wxr1[tid] = W_wr[(j0 + tid) * 2 + 1];
        wxh0[tid] = W_wh[(j0 + tid) * 2 + 0];
        wxh1[tid] = W_wh[(j0 + tid) * 2 + 1];
    }
    group_barrier(gm, bidx);  // h0 visible group-wide
    issue_stage(g_h, smu + HS_OFF, x, smu + XT_OFF, b0, 0, true, tid);

    for (int t = 0; t < TT; t++) {
        // ---------------- phase 1: z, r, r*h ----------------
        CP_WAIT0();
        __syncthreads();
        {
            u64 aZ[4][2], aR[4][2];
#pragma unroll
            for (int r = 0; r < 4; r++) {
                aZ[r][0] = 0ull; aZ[r][1] = 0ull;
                aR[r][0] = 0ull; aR[r][1] = 0ull;
            }
#pragma unroll 8
            for (int k4 = 32 * kq; k4 < 32 * kq + 32; k4++) {
                ulonglong2 h0v = *(const ulonglong2*)(hbase + 0 * HS_STRIDE + k4 * 16);
                ulonglong2 h1v = *(const ulonglong2*)(hbase + 1 * HS_STRIDE + k4 * 16);
                ulonglong2 h2v = *(const ulonglong2*)(hbase + 2 * HS_STRIDE + k4 * 16);
                ulonglong2 h3v = *(const ulonglong2*)(hbase + 3 * HS_STRIDE + k4 * 16);
                ulonglong2 wA0 = WZRu2[(2 * k4) * 16 + n0];
                ulonglong2 wA1 = WZRu2[(2 * k4) * 16 + n1];
                ulonglong2 wB0 = WZRu2[(2 * k4 + 1) * 16 + n0];
                ulonglong2 wB1 = WZRu2[(2 * k4 + 1) * 16 + n1];
                aZ[0][0] = ffma2(h0v.x, wA0.x, aZ[0][0]);
                aR[0][0] = ffma2(h0v.x, wA0.y, aR[0][0]);
                aZ[0][1] = ffma2(h0v.x, wA1.x, aZ[0][1]);
                aR[0][1] = ffma2(h0v.x, wA1.y, aR[0][1]);
                aZ[1][0] = ffma2(h1v.x, wA0.x, aZ[1][0]);
                aR[1][0] = ffma2(h1v.x, wA0.y, aR[1][0]);
                aZ[1][1] = ffma2(h1v.x, wA1.x, aZ[1][1]);
                aR[1][1] = ffma2(h1v.x, wA1.y, aR[1][1]);
                aZ[2][0] = ffma2(h2v.x, wA0.x, aZ[2][0]);
                aR[2][0] = ffma2(h2v.x, wA0.y, aR[2][0]);
                aZ[2][1] = ffma2(h2v.x, wA1.x, aZ[2][1]);
                aR[2][1] = ffma2(h2v.x, wA1.y, aR[2][1]);
                aZ[3][0] = ffma2(h3v.x, wA0.x, aZ[3][0]);
                aR[3][0] = ffma2(h3v.x, wA0.y, aR[3][0]);
                aZ[3][1] = ffma2(h3v.x, wA1.x, aZ[3][1]);
                aR[3][1] = ffma2(h3v.x, wA1.y, aR[3][1]);
                aZ[0][0] = ffma2(h0v.y, wB0.x, aZ[0][0]);
                aR[0][0] = ffma2(h0v.y, wB0.y, aR[0][0]);
                aZ[0][1] = ffma2(h0v.y, wB1.x, aZ[0][1]);
                aR[0][1] = ffma2(h0v.y, wB1.y, aR[0][1]);
                aZ[1][0] = ffma2(h1v.y, wB0.x, aZ[1][0]);
                aR[1][0] = ffma2(h1v.y, wB0.y, aR[1][0]);
                aZ[1][1] = ffma2(h1v.y, wB1.x, aZ[1][1]);
                aR[1][1] = ffma2(h1v.y, wB1.y, aR[1][1]);
                aZ[2][0] = ffma2(h2v.y, wB0.x, aZ[2][0]);
                aR[2][0] = ffma2(h2v.y, wB0.y, aR[2][0]);
                aZ[2][1] = ffma2(h2v.y, wB1.x, aZ[2][1]);
                aR[2][1] = ffma2(h2v.y, wB1.y, aR[2][1]);
                aZ[3][0] = ffma2(h3v.y, wB0.x, aZ[3][0]);
                aR[3][0] = ffma2(h3v.y, wB0.y, aR[3][0]);
                aZ[3][1] = ffma2(h3v.y, wB1.x, aZ[3][1]);
                aR[3][1] = ffma2(h3v.y, wB1.y, aR[3][1]);
            }
#pragma unroll
            for (int r = 0; r < 4; r++)
#pragma unroll
                for (int n = 0; n < 2; n++) {
                    float2 tz = unpack2(aZ[r][n]);
                    float2 tr = unpack2(aR[r][n]);
                    PART[(kq * 64 + u) * 8 + r * 2 + n] =
                        pack2(tz.x + tz.y, tr.x + tr.y);
                }
        }
        __syncthreads();
#pragma unroll
        for (int it = 0; it < 2; it++) {
            int j = 2 * tid + it;
            int row = j >> 4, c = j & 15;
            int uu = (row >> 2) * 8 + (c >> 1);
            int ii = (row & 3) * 2 + (c & 1);
            u64 s = addf2(addf2(PART[uu * 8 + ii], PART[(64 + uu) * 8 + ii]),
                          addf2(PART[(128 + uu) * 8 + ii],
                                PART[(192 + uu) * 8 + ii]));
            float2 zr = unpack2(s);
            float2 xt = xts[row];
            float zp = zr.x + xt.x * wxz0[c] + xt.y * wxz1[c];
            float rp = zr.y + xt.x * wxr0[c] + xt.y * wxr1[c];
            float z = 1.f / (1.f + __expf(-zp));
            float r = 1.f / (1.f + __expf(-rp));
            float hown = *(const float*)(smem + HS_OFF + row * HS_STRIDE +
                                         (size_t)(j0 + c) * 4);
            ZBUF[row * 16 + c] = pack2(z, hown);
            g_rh[(size_t)(b0 + row) * NR + j0 + c] = r * hown;
        }

        group_barrier(gm, bidx);  // rh visible group-wide
        issue_stage(g_rh, smu + HS_OFF, x, smu + XT_OFF, b0, 0, false, tid);

        // ---------------- phase 2: u, tanh, h update ----------------
        CP_WAIT0();
        __syncthreads();
        {
            u64 acc[4][2];
            dot_wh4(hbase, WHu2, jp, kq, acc);
#pragma unroll
            for (int r = 0; r < 4; r++)
#pragma unroll
                for (int n = 0; n < 2; n++) {
                    float2 t2 = unpack2(acc[r][n]);
                    PARTF[(kq * 64 + u) * 8 + r * 2 + n] = t2.x + t2.y;
                }
        }
        __syncthreads();
#pragma unroll
        for (int it = 0; it < 2; it++) {
            int j = 2 * tid + it;
            int row = j >> 4, c = j & 15;
            int uu = (row >> 2) * 8 + (c >> 1);
            int ii = (row & 3) * 2 + (c & 1);
            float s = PARTF[uu * 8 + ii] + PARTF[(64 + uu) * 8 + ii] +
                      PARTF[(128 + uu) * 8 + ii] + PARTF[(192 + uu) * 8 + ii];
            float2 xt = xts[row];
            float up = s + xt.x * wxh0[c] + xt.y * wxh1[c];
            float th = tanhf(up);
            float2 zh = unpack2(ZBUF[row * 16 + c]);
            float hn = zh.y + DT_TAU * (zh.x - 1.f) * (zh.y - th);
            g_h[(size_t)(b0 + row) * NR + j0 + c] = hn;
            out_h[((size_t)(b0 + row) * TT + t) * NR + j0 + c] = hn;
        }

        group_barrier(gm, bidx);  // h(t+1) visible group-wide
        if (t + 1 < TT)
            issue_stage(g_h, smu + HS_OFF, x, smu + XT_OFF, b0, t + 1, true, tid);
    }
}

// ---------------- decoder: y = h @ W_dec^T  (f32x2 tiled GEMM) ----------------
__global__ void __launch_bounds__(256)
decoder_kernel(const float* __restrict__ h, const float* __restrict__ W,
               float* __restrict__ y) {
    __shared__ float HT[32 * 132];
    __shared__ float WT[32 * 68];
    const int tid = threadIdx.x;
    const int bt0 = blockIdx.x * 128;
    const int o0  = blockIdx.y * 64;
    const int rg = tid & 15;
    const int cg = tid >> 4;
    const int col0 = cg * 4;
    const int lrow = tid >> 1, lkh = (tid & 1) * 16;
    const int lcol = tid >> 2, lkw = (tid & 3) * 8;

    u64 acc[4][4];
#pragma unroll
    for (int i = 0; i < 4; i++)
#pragma unroll
        for (int c = 0; c < 4; c++) acc[i][c] = 0ull;

    for (int k0 = 0; k0 < NR; k0 += 32) {
        __syncthreads();
        const float4* hsrc =
            (const float4*)(h + (size_t)(bt0 + lrow) * NR + k0 + lkh);
#pragma unroll
        for (int j = 0; j < 4; j++) {
            float4 v = hsrc[j];
            int kk = lkh + 4 * j;
            HT[(kk + 0) * 132 + lrow] = v.x;
            HT[(kk + 1) * 132 + lrow] = v.y;
            HT[(kk + 2) * 132 + lrow] = v.z;
            HT[(kk + 3) * 132 + lrow] = v.w;
        }
        const float4* wsrc =
            (const float4*)(W + (size_t)(o0 + lcol) * NR + k0 + lkw);
#pragma unroll
        for (int j = 0; j < 2; j++) {
            float4 v = wsrc[j];
            int kk = lkw + 4 * j;
            WT[(kk + 0) * 68 + lcol] = v.x;
            WT[(kk + 1) * 68 + lcol] = v.y;
            WT[(kk + 2) * 68 + lcol] = v.z;
            WT[(kk + 3) * 68 + lcol] = v.w;
        }
        __syncthreads();
#pragma unroll 4
        for (int k = 0; k < 32; k++) {
            const u64* HTd = (const u64*)(HT + k * 132);
            u64 h0 = HTd[rg];
            u64 h1 = HTd[rg + 16];
            u64 h2 = HTd[rg + 32];
            u64 h3 = HTd[rg + 48];
            float4 wv = *(const float4*)(WT + k * 68 + col0);
            u64 w0 = pack2(wv.x, wv.x);
            u64 w1 = pack2(wv.y, wv.y);
            u64 w2 = pack2(wv.z, wv.z);
            u64 w3 = pack2(wv.w, wv.w);
            acc[0][0] = ffma2(h0, w0, acc[0][0]);
            acc[0][1] = ffma2(h0, w1, acc[0][1]);
            acc[0][2] = ffma2(h0, w2, acc[0][2]);
            acc[0][3] = ffma2(h0, w3, acc[0][3]);
            acc[1][0] = ffma2(h1, w0, acc[1][0]);
            acc[1][1] = ffma2(h1, w1, acc[1][1]);
            acc[1][2] = ffma2(h1, w2, acc[1][2]);
            acc[1][3] = ffma2(h1, w3, acc[1][3]);
            acc[2][0] = ffma2(h2, w0, acc[2][0]);
            acc[2][1] = ffma2(h2, w1, acc[2][1]);
            acc[2][2] = ffma2(h2, w2, acc[2][2]);
            acc[2][3] = ffma2(h2, w3, acc[2][3]);
            acc[3][0] = ffma2(h3, w0, acc[3][0]);
            acc[3][1] = ffma2(h3, w1, acc[3][1]);
            acc[3][2] = ffma2(h3, w2, acc[3][2]);
            acc[3][3] = ffma2(h3, w3, acc[3][3]);
        }
    }
#pragma unroll
    for (int i = 0; i < 4; i++) {
        int r = 2 * rg + 32 * i;
        float2 p0 = unpack2(acc[i][0]);
        float2 p1 = unpack2(acc[i][1]);
        float2 p2 = unpack2(acc[i][2]);
        float2 p3 = unpack2(acc[i][3]);
        float4 ra = make_float4(p0.x, p1.x, p2.x, p3.x);
        float4 rb = make_float4(p0.y, p1.y, p2.y, p3.y);
        *(float4*)(y + (size_t)(bt0 + r) * NOUT + o0 + col0) = ra;
        *(float4*)(y + (size_t)(bt0 + r + 1) * NOUT + o0 + col0) = rb;
    }
}

// ---------------- launch -------------------------------------------------------
extern "C" void kernel_launch(void* const* d_in, const int* in_sizes, int n_in,
                              void* d_out, int out_size) {
    const float* x          = (const float*)d_in[0];
    const float* init_state = (const float*)d_in[1];
    const float* W_enc      = (const float*)d_in[2];
    const float* W_wz       = (const float*)d_in[3];
    const float* W_uz       = (const float*)d_in[4];
    const float* W_wr       = (const float*)d_in[5];
    const float* W_ur       = (const float*)d_in[6];
    const float* W_wh       = (const float*)d_in[7];
    const float* W_uh       = (const float*)d_in[8];
    const float* W_dec      = (const float*)d_in[9];
    float* out = (float*)d_out;

    cudaFuncSetAttribute(rnn_persistent,
                         cudaFuncAttributeMaxDynamicSharedMemorySize, SMEM_TOTAL);

    rnn_persistent<<<PM * PN, NTH, SMEM_TOTAL>>>(
        x, init_state, W_enc, W_wz, W_uz, W_wr, W_ur, W_wh, W_uh, out);

    size_t hN = (size_t)BN * TT * NR;
    if ((size_t)out_size >= 2 * hN) {
        dim3 grid((BN * TT) / 128, NOUT / 64);
        decoder_kernel<<<grid, 256>>>(out, W_dec, out + hN);
    }

    reset_bar_kernel<<<1, 32>>>();
}